// round 1
// baseline (speedup 1.0000x reference)
#include <cuda_runtime.h>
#include <math_constants.h>

// Problem constants
#define Bd   8
#define Td   1024
#define Cd   768
#define Hd   12
#define HDd  64
#define C3   2304   // 3*C

// Scratch (allocation-free rule: __device__ globals)
__device__ float g_qkv[(size_t)Bd * Td * C3];   // [B,T,3C]
__device__ float g_y  [(size_t)Bd * Td * Cd];   // [B,T,C] attention output (pre-proj)

// ---------------------------------------------------------------------------
// Tiled fp32 SGEMM with bias:  C[M,N] = A[M,K] @ B[K,N] + bias[N]
// 64x64 block tile, BK=16, 4x4 per-thread tile, 256 threads.
// ---------------------------------------------------------------------------
#define BM 64
#define BN 64
#define BK 16

__global__ __launch_bounds__(256) void sgemm_bias(
    const float* __restrict__ A,
    const float* __restrict__ Bm,
    const float* __restrict__ bias,
    float* __restrict__ Cm,
    int M, int N, int K)
{
    __shared__ float As[BK][BM];   // stored transposed: As[k][m]
    __shared__ float Bs[BK][BN];

    const int tx = threadIdx.x;         // 0..15
    const int ty = threadIdx.y;         // 0..15
    const int tid = ty * 16 + tx;       // 0..255
    const int m0 = blockIdx.y * BM;
    const int n0 = blockIdx.x * BN;

    // A tile load mapping: 64 rows x 16 cols = 256 float4
    const int a_row = tid >> 2;            // 0..63
    const int a_c4  = (tid & 3) * 4;       // 0,4,8,12
    // B tile load mapping: 16 rows x 64 cols = 256 float4
    const int b_row = tid >> 4;            // 0..15
    const int b_c4  = (tid & 15) * 4;      // 0..60

    float acc[4][4];
#pragma unroll
    for (int i = 0; i < 4; i++)
#pragma unroll
        for (int j = 0; j < 4; j++) acc[i][j] = 0.0f;

    for (int k0 = 0; k0 < K; k0 += BK) {
        float4 av = *(const float4*)&A[(size_t)(m0 + a_row) * K + k0 + a_c4];
        As[a_c4 + 0][a_row] = av.x;
        As[a_c4 + 1][a_row] = av.y;
        As[a_c4 + 2][a_row] = av.z;
        As[a_c4 + 3][a_row] = av.w;

        float4 bv = *(const float4*)&Bm[(size_t)(k0 + b_row) * N + n0 + b_c4];
        *(float4*)&Bs[b_row][b_c4] = bv;

        __syncthreads();

#pragma unroll
        for (int kk = 0; kk < BK; kk++) {
            float4 a4 = *(const float4*)&As[kk][ty * 4];
            float4 b4 = *(const float4*)&Bs[kk][tx * 4];
            float ar[4] = {a4.x, a4.y, a4.z, a4.w};
            float br[4] = {b4.x, b4.y, b4.z, b4.w};
#pragma unroll
            for (int i = 0; i < 4; i++)
#pragma unroll
                for (int j = 0; j < 4; j++)
                    acc[i][j] += ar[i] * br[j];
        }
        __syncthreads();
    }

    // Epilogue: add bias and store
    float4 bb = *(const float4*)&bias[n0 + tx * 4];
#pragma unroll
    for (int i = 0; i < 4; i++) {
        const int m = m0 + ty * 4 + i;
        float4 o;
        o.x = acc[i][0] + bb.x;
        o.y = acc[i][1] + bb.y;
        o.z = acc[i][2] + bb.z;
        o.w = acc[i][3] + bb.w;
        *(float4*)&Cm[(size_t)m * N + n0 + tx * 4] = o;
    }
}

// ---------------------------------------------------------------------------
// Flash-style causal attention (fp32).
// qkv layout: [B, T, 3C] where per token, head h occupies cols
//   [h*192, h*192+64) = q, [+64,+128) = k, [+128,+192) = v
// One block per (b, h, q-tile of 64 rows). 64 threads; thread t owns q-row t.
// Output y[b, t, h*64 + d].
// ---------------------------------------------------------------------------
__global__ __launch_bounds__(64) void attn_kernel(
    const float* __restrict__ qkv, float* __restrict__ y)
{
    __shared__ float Ks[64 * 64];
    __shared__ float Vs[64 * 64];
    __shared__ float Ss[64 * 64];   // scores stored transposed: Ss[j*64 + t]

    const int t  = threadIdx.x;     // 0..63 (q row within tile)
    const int qt = blockIdx.x;      // q tile index
    const int h  = blockIdx.y;
    const int b  = blockIdx.z;
    const int q0 = qt * 64;

    const float* base = qkv + (size_t)b * Td * C3 + h * 192;

    // Load q row into registers, pre-scaled by 1/sqrt(HD)=0.125
    float4 qv[16];
    {
        const float4* qrow = (const float4*)(base + (size_t)(q0 + t) * C3);
#pragma unroll
        for (int i = 0; i < 16; i++) {
            float4 v = qrow[i];
            v.x *= 0.125f; v.y *= 0.125f; v.z *= 0.125f; v.w *= 0.125f;
            qv[i] = v;
        }
    }

    float o[64];
#pragma unroll
    for (int d = 0; d < 64; d++) o[d] = 0.0f;
    float m = -CUDART_INF_F;
    float l = 0.0f;

    for (int kt = 0; kt <= qt; kt++) {
        const int k0 = kt * 64;
        // Cooperative K/V tile load (coalesced: 16 threads x float4 per row seg)
#pragma unroll
        for (int it = 0; it < 16; it++) {
            const int idx = it * 64 + t;         // 0..1023
            const int row = idx >> 4;            // 0..63
            const int c4  = (idx & 15) * 4;      // 0..60
            const float* src = base + (size_t)(k0 + row) * C3;
            *(float4*)&Ks[row * 64 + c4] = *(const float4*)(src + 64 + c4);
            *(float4*)&Vs[row * 64 + c4] = *(const float4*)(src + 128 + c4);
        }
        __syncthreads();

        const bool diag = (kt == qt);
        float mt = -CUDART_INF_F;

        // Scores s_j = q . k_j  (4 accumulators for ILP)
        for (int j = 0; j < 64; j++) {
            const float4* kr = (const float4*)&Ks[j * 64];
            float s0 = 0.f, s1 = 0.f, s2 = 0.f, s3 = 0.f;
#pragma unroll
            for (int i = 0; i < 16; i++) {
                float4 kv4 = kr[i];
                s0 += qv[i].x * kv4.x;
                s1 += qv[i].y * kv4.y;
                s2 += qv[i].z * kv4.z;
                s3 += qv[i].w * kv4.w;
            }
            float s = (s0 + s1) + (s2 + s3);
            if (diag && j > t) s = -CUDART_INF_F;
            Ss[j * 64 + t] = s;
            mt = fmaxf(mt, s);
        }

        const float mn   = fmaxf(m, mt);
        const float corr = __expf(m - mn);
        l *= corr;
#pragma unroll
        for (int d = 0; d < 64; d++) o[d] *= corr;

        for (int j = 0; j < 64; j++) {
            const float p = __expf(Ss[j * 64 + t] - mn);
            l += p;
            const float4* vr = (const float4*)&Vs[j * 64];
#pragma unroll
            for (int i = 0; i < 16; i++) {
                float4 vv = vr[i];
                o[i * 4 + 0] += p * vv.x;
                o[i * 4 + 1] += p * vv.y;
                o[i * 4 + 2] += p * vv.z;
                o[i * 4 + 3] += p * vv.w;
            }
        }
        m = mn;
        __syncthreads();
    }

    const float inv = 1.0f / l;
    float* yr = y + ((size_t)b * Td + q0 + t) * Cd + h * HDd;
#pragma unroll
    for (int i = 0; i < 16; i++) {
        float4 ov;
        ov.x = o[i * 4 + 0] * inv;
        ov.y = o[i * 4 + 1] * inv;
        ov.z = o[i * 4 + 2] * inv;
        ov.w = o[i * 4 + 3] * inv;
        *(float4*)&yr[i * 4] = ov;
    }
}

// ---------------------------------------------------------------------------
extern "C" void kernel_launch(void* const* d_in, const int* in_sizes, int n_in,
                              void* d_out, int out_size)
{
    const float* x  = (const float*)d_in[0];   // [8,1024,768]
    const float* Wa = (const float*)d_in[1];   // [768,2304]
    const float* ba = (const float*)d_in[2];   // [2304]
    const float* Wp = (const float*)d_in[3];   // [768,768]
    const float* bp = (const float*)d_in[4];   // [768]
    float* out = (float*)d_out;                // [8,1024,768]

    float *qkv_ptr = nullptr, *y_ptr = nullptr;
    cudaGetSymbolAddress((void**)&qkv_ptr, g_qkv);
    cudaGetSymbolAddress((void**)&y_ptr, g_y);

    dim3 blk(16, 16);

    // 1) qkv = x @ W_attn + b_attn   (M=8192, N=2304, K=768)
    sgemm_bias<<<dim3(C3 / BN, (Bd * Td) / BM), blk>>>(x, Wa, ba, qkv_ptr,
                                                       Bd * Td, C3, Cd);
    // 2) causal attention -> y
    attn_kernel<<<dim3(Td / 64, Hd, Bd), 64>>>(qkv_ptr, y_ptr);

    // 3) out = y @ W_proj + b_proj   (M=8192, N=768, K=768)
    sgemm_bias<<<dim3(Cd / BN, (Bd * Td) / BM), blk>>>(y_ptr, Wp, bp, out,
                                                       Bd * Td, Cd, Cd);
}

// round 2
// speedup vs baseline: 1.5798x; 1.5798x over previous
#include <cuda_runtime.h>
#include <math_constants.h>
#include <cstdint>

// Problem constants
#define Bd   8
#define Td   1024
#define Cd   768
#define Hd   12
#define HDd  64
#define C3   2304   // 3*C

// Scratch (allocation-free rule: __device__ globals)
__device__ float g_qkv[(size_t)Bd * Td * C3];   // [B,T,3C]
__device__ float g_y  [(size_t)Bd * Td * Cd];   // [B,T,C] attention output (pre-proj)

// ---------------------------------------------------------------------------
// TF32 tensor-core GEMM with bias: C[M,N] = A[M,K] @ B[K,N] + bias[N]
// Block tile 128x128, BK=16, 8 warps (256 thr), warp tile 64x32,
// mma.sync.aligned.m16n8k8.row.col.f32.tf32.tf32.f32
// ---------------------------------------------------------------------------
#define GBM 128
#define GBN 128
#define GBK 16
#define SPAD 132   // padded row length (floats); 132*4B = 528B, 16B-aligned, kills LDS conflicts

__device__ __forceinline__ float to_tf32(float x) {
    float r;
    asm("cvt.rna.tf32.f32 %0, %1;" : "=f"(r) : "f"(x));
    return r;
}

__device__ __forceinline__ void mma_tf32(float c[4],
                                         uint32_t a0, uint32_t a1, uint32_t a2, uint32_t a3,
                                         uint32_t b0, uint32_t b1) {
    asm volatile(
        "mma.sync.aligned.m16n8k8.row.col.f32.tf32.tf32.f32 "
        "{%0,%1,%2,%3}, {%4,%5,%6,%7}, {%8,%9}, {%0,%1,%2,%3};"
        : "+f"(c[0]), "+f"(c[1]), "+f"(c[2]), "+f"(c[3])
        : "r"(a0), "r"(a1), "r"(a2), "r"(a3), "r"(b0), "r"(b1));
}

__global__ __launch_bounds__(256) void gemm_tf32_bias(
    const float* __restrict__ A,
    const float* __restrict__ Bm,
    const float* __restrict__ bias,
    float* __restrict__ Cm,
    int M, int N, int K)
{
    __shared__ float As[GBK][SPAD];   // As[k][m]
    __shared__ float Bs[GBK][SPAD];   // Bs[k][n]

    const int tid  = threadIdx.x;
    const int wid  = tid >> 5;
    const int lane = tid & 31;
    const int grp  = lane >> 2;   // 0..7
    const int tig  = lane & 3;    // 0..3

    const int m0 = blockIdx.y * GBM;
    const int n0 = blockIdx.x * GBN;

    const int wm = (wid & 1) * 64;   // warp m-offset within block tile
    const int wn = (wid >> 1) * 32;  // warp n-offset within block tile

    float acc[4][4][4];
#pragma unroll
    for (int i = 0; i < 4; i++)
#pragma unroll
        for (int j = 0; j < 4; j++)
#pragma unroll
            for (int r = 0; r < 4; r++) acc[i][j][r] = 0.0f;

    for (int k0 = 0; k0 < K; k0 += GBK) {
        // --- load A tile (128 x 16) transposed into As[k][m], tf32-rounded ---
#pragma unroll
        for (int r = 0; r < 2; r++) {
            const int idx = tid + r * 256;        // 0..511
            const int row = idx >> 2;             // 0..127
            const int c4  = (idx & 3) * 4;        // 0,4,8,12
            float4 v = *(const float4*)&A[(size_t)(m0 + row) * K + k0 + c4];
            As[c4 + 0][row] = to_tf32(v.x);
            As[c4 + 1][row] = to_tf32(v.y);
            As[c4 + 2][row] = to_tf32(v.z);
            As[c4 + 3][row] = to_tf32(v.w);
        }
        // --- load B tile (16 x 128) into Bs[k][n], tf32-rounded ---
#pragma unroll
        for (int r = 0; r < 2; r++) {
            const int idx = tid + r * 256;        // 0..511
            const int row = idx >> 5;             // 0..15
            const int c4  = (idx & 31) * 4;       // 0..124
            float4 v = *(const float4*)&Bm[(size_t)(k0 + row) * N + n0 + c4];
            float4 w;
            w.x = to_tf32(v.x); w.y = to_tf32(v.y);
            w.z = to_tf32(v.z); w.w = to_tf32(v.w);
            *(float4*)&Bs[row][c4] = w;
        }
        __syncthreads();

#pragma unroll
        for (int ks = 0; ks < 2; ks++) {
            const int kb = ks * 8;
            uint32_t afr[4][4];
            uint32_t bfr[4][2];
#pragma unroll
            for (int mf = 0; mf < 4; mf++) {
                const int m = wm + mf * 16;
                afr[mf][0] = __float_as_uint(As[kb + tig    ][m + grp    ]);
                afr[mf][1] = __float_as_uint(As[kb + tig    ][m + grp + 8]);
                afr[mf][2] = __float_as_uint(As[kb + tig + 4][m + grp    ]);
                afr[mf][3] = __float_as_uint(As[kb + tig + 4][m + grp + 8]);
            }
#pragma unroll
            for (int nf = 0; nf < 4; nf++) {
                const int n = wn + nf * 8;
                bfr[nf][0] = __float_as_uint(Bs[kb + tig    ][n + grp]);
                bfr[nf][1] = __float_as_uint(Bs[kb + tig + 4][n + grp]);
            }
#pragma unroll
            for (int mf = 0; mf < 4; mf++)
#pragma unroll
                for (int nf = 0; nf < 4; nf++)
                    mma_tf32(acc[mf][nf],
                             afr[mf][0], afr[mf][1], afr[mf][2], afr[mf][3],
                             bfr[nf][0], bfr[nf][1]);
        }
        __syncthreads();
    }

    // --- epilogue: bias + store (float2 per row pair) ---
#pragma unroll
    for (int nf = 0; nf < 4; nf++) {
        const int col = n0 + wn + nf * 8 + tig * 2;
        const float bx = bias[col];
        const float by = bias[col + 1];
#pragma unroll
        for (int mf = 0; mf < 4; mf++) {
            const int row0 = m0 + wm + mf * 16 + grp;
            const int row1 = row0 + 8;
            float2 o0, o1;
            o0.x = acc[mf][nf][0] + bx;
            o0.y = acc[mf][nf][1] + by;
            o1.x = acc[mf][nf][2] + bx;
            o1.y = acc[mf][nf][3] + by;
            *(float2*)&Cm[(size_t)row0 * N + col] = o0;
            *(float2*)&Cm[(size_t)row1 * N + col] = o1;
        }
    }
}

// ---------------------------------------------------------------------------
// Flash-style causal attention (fp32) — unchanged from R1 (known correct).
// ---------------------------------------------------------------------------
__global__ __launch_bounds__(64) void attn_kernel(
    const float* __restrict__ qkv, float* __restrict__ y)
{
    __shared__ float Ks[64 * 64];
    __shared__ float Vs[64 * 64];
    __shared__ float Ss[64 * 64];   // scores stored transposed: Ss[j*64 + t]

    const int t  = threadIdx.x;     // 0..63 (q row within tile)
    const int qt = blockIdx.x;      // q tile index
    const int h  = blockIdx.y;
    const int b  = blockIdx.z;
    const int q0 = qt * 64;

    const float* base = qkv + (size_t)b * Td * C3 + h * 192;

    float4 qv[16];
    {
        const float4* qrow = (const float4*)(base + (size_t)(q0 + t) * C3);
#pragma unroll
        for (int i = 0; i < 16; i++) {
            float4 v = qrow[i];
            v.x *= 0.125f; v.y *= 0.125f; v.z *= 0.125f; v.w *= 0.125f;
            qv[i] = v;
        }
    }

    float o[64];
#pragma unroll
    for (int d = 0; d < 64; d++) o[d] = 0.0f;
    float m = -CUDART_INF_F;
    float l = 0.0f;

    for (int kt = 0; kt <= qt; kt++) {
        const int k0 = kt * 64;
#pragma unroll
        for (int it = 0; it < 16; it++) {
            const int idx = it * 64 + t;
            const int row = idx >> 4;
            const int c4  = (idx & 15) * 4;
            const float* src = base + (size_t)(k0 + row) * C3;
            *(float4*)&Ks[row * 64 + c4] = *(const float4*)(src + 64 + c4);
            *(float4*)&Vs[row * 64 + c4] = *(const float4*)(src + 128 + c4);
        }
        __syncthreads();

        const bool diag = (kt == qt);
        float mt = -CUDART_INF_F;

        for (int j = 0; j < 64; j++) {
            const float4* kr = (const float4*)&Ks[j * 64];
            float s0 = 0.f, s1 = 0.f, s2 = 0.f, s3 = 0.f;
#pragma unroll
            for (int i = 0; i < 16; i++) {
                float4 kv4 = kr[i];
                s0 += qv[i].x * kv4.x;
                s1 += qv[i].y * kv4.y;
                s2 += qv[i].z * kv4.z;
                s3 += qv[i].w * kv4.w;
            }
            float s = (s0 + s1) + (s2 + s3);
            if (diag && j > t) s = -CUDART_INF_F;
            Ss[j * 64 + t] = s;
            mt = fmaxf(mt, s);
        }

        const float mn   = fmaxf(m, mt);
        const float corr = __expf(m - mn);
        l *= corr;
#pragma unroll
        for (int d = 0; d < 64; d++) o[d] *= corr;

        for (int j = 0; j < 64; j++) {
            const float p = __expf(Ss[j * 64 + t] - mn);
            l += p;
            const float4* vr = (const float4*)&Vs[j * 64];
#pragma unroll
            for (int i = 0; i < 16; i++) {
                float4 vv = vr[i];
                o[i * 4 + 0] += p * vv.x;
                o[i * 4 + 1] += p * vv.y;
                o[i * 4 + 2] += p * vv.z;
                o[i * 4 + 3] += p * vv.w;
            }
        }
        m = mn;
        __syncthreads();
    }

    const float inv = 1.0f / l;
    float* yr = y + ((size_t)b * Td + q0 + t) * Cd + h * HDd;
#pragma unroll
    for (int i = 0; i < 16; i++) {
        float4 ov;
        ov.x = o[i * 4 + 0] * inv;
        ov.y = o[i * 4 + 1] * inv;
        ov.z = o[i * 4 + 2] * inv;
        ov.w = o[i * 4 + 3] * inv;
        *(float4*)&yr[i * 4] = ov;
    }
}

// ---------------------------------------------------------------------------
extern "C" void kernel_launch(void* const* d_in, const int* in_sizes, int n_in,
                              void* d_out, int out_size)
{
    const float* x  = (const float*)d_in[0];   // [8,1024,768]
    const float* Wa = (const float*)d_in[1];   // [768,2304]
    const float* ba = (const float*)d_in[2];   // [2304]
    const float* Wp = (const float*)d_in[3];   // [768,768]
    const float* bp = (const float*)d_in[4];   // [768]
    float* out = (float*)d_out;                // [8,1024,768]

    float *qkv_ptr = nullptr, *y_ptr = nullptr;
    cudaGetSymbolAddress((void**)&qkv_ptr, g_qkv);
    cudaGetSymbolAddress((void**)&y_ptr, g_y);

    // 1) qkv = x @ W_attn + b_attn   (M=8192, N=2304, K=768)
    gemm_tf32_bias<<<dim3(C3 / GBN, (Bd * Td) / GBM), 256>>>(x, Wa, ba, qkv_ptr,
                                                             Bd * Td, C3, Cd);
    // 2) causal attention -> y
    attn_kernel<<<dim3(Td / 64, Hd, Bd), 64>>>(qkv_ptr, y_ptr);

    // 3) out = y @ W_proj + b_proj   (M=8192, N=768, K=768)
    gemm_tf32_bias<<<dim3(Cd / GBN, (Bd * Td) / GBM), 256>>>(y_ptr, Wp, bp, out,
                                                             Bd * Td, Cd, Cd);
}

// round 3
// speedup vs baseline: 2.8339x; 1.7938x over previous
#include <cuda_runtime.h>
#include <math_constants.h>
#include <cstdint>

// Problem constants
#define Bd   8
#define Td   1024
#define Cd   768
#define Hd   12
#define HDd  64
#define C3   2304   // 3*C

__device__ float g_qkv[(size_t)Bd * Td * C3];   // [B,T,3C]
__device__ float g_y  [(size_t)Bd * Td * Cd];   // [B,T,C]

__device__ __forceinline__ float to_tf32(float x) {
    float r;
    asm("cvt.rna.tf32.f32 %0, %1;" : "=f"(r) : "f"(x));
    return r;
}

__device__ __forceinline__ void mma_tf32(float c[4],
                                         uint32_t a0, uint32_t a1, uint32_t a2, uint32_t a3,
                                         uint32_t b0, uint32_t b1) {
    asm volatile(
        "mma.sync.aligned.m16n8k8.row.col.f32.tf32.tf32.f32 "
        "{%0,%1,%2,%3}, {%4,%5,%6,%7}, {%8,%9}, {%0,%1,%2,%3};"
        : "+f"(c[0]), "+f"(c[1]), "+f"(c[2]), "+f"(c[3])
        : "r"(a0), "r"(a1), "r"(a2), "r"(a3), "r"(b0), "r"(b1));
}

// ---------------------------------------------------------------------------
// TF32 GEMM + bias, double-buffered smem. C[M,N] = A[M,K] @ B[K,N] + bias[N]
// ---------------------------------------------------------------------------
#define GBM 128
#define GBN 128
#define GBK 16
#define SPAD 132

__global__ __launch_bounds__(256) void gemm_tf32_bias(
    const float* __restrict__ A,
    const float* __restrict__ Bm,
    const float* __restrict__ bias,
    float* __restrict__ Cm,
    int M, int N, int K)
{
    __shared__ float As[2][GBK][SPAD];
    __shared__ float Bs[2][GBK][SPAD];

    const int tid  = threadIdx.x;
    const int wid  = tid >> 5;
    const int lane = tid & 31;
    const int grp  = lane >> 2;
    const int tig  = lane & 3;

    const int m0 = blockIdx.y * GBM;
    const int n0 = blockIdx.x * GBN;
    const int wm = (wid & 1) * 64;
    const int wn = (wid >> 1) * 32;

    float acc[4][4][4];
#pragma unroll
    for (int i = 0; i < 4; i++)
#pragma unroll
        for (int j = 0; j < 4; j++)
#pragma unroll
            for (int r = 0; r < 4; r++) acc[i][j][r] = 0.0f;

    // Prologue: tile 0 -> buffer 0
#pragma unroll
    for (int r = 0; r < 2; r++) {
        const int idx = tid + r * 256;
        {
            const int row = idx >> 2, c4 = (idx & 3) * 4;
            float4 v = *(const float4*)&A[(size_t)(m0 + row) * K + c4];
            As[0][c4 + 0][row] = to_tf32(v.x);
            As[0][c4 + 1][row] = to_tf32(v.y);
            As[0][c4 + 2][row] = to_tf32(v.z);
            As[0][c4 + 3][row] = to_tf32(v.w);
        }
        {
            const int row = idx >> 5, c4 = (idx & 31) * 4;
            float4 v = *(const float4*)&Bm[(size_t)row * N + n0 + c4];
            float4 w;
            w.x = to_tf32(v.x); w.y = to_tf32(v.y);
            w.z = to_tf32(v.z); w.w = to_tf32(v.w);
            *(float4*)&Bs[0][row][c4] = w;
        }
    }
    __syncthreads();

    const int nk = K / GBK;
    for (int t = 0; t < nk; t++) {
        const int cur = t & 1;
        float4 pav[2], pbv[2];
        const bool pf = (t + 1 < nk);
        if (pf) {
            const int k0 = (t + 1) * GBK;
#pragma unroll
            for (int r = 0; r < 2; r++) {
                const int idx = tid + r * 256;
                const int arow = idx >> 2, ac4 = (idx & 3) * 4;
                pav[r] = *(const float4*)&A[(size_t)(m0 + arow) * K + k0 + ac4];
                const int brow = idx >> 5, bc4 = (idx & 31) * 4;
                pbv[r] = *(const float4*)&Bm[(size_t)(k0 + brow) * N + n0 + bc4];
            }
        }

#pragma unroll
        for (int ks = 0; ks < 2; ks++) {
            const int kb = ks * 8;
            uint32_t afr[4][4];
            uint32_t bfr[4][2];
#pragma unroll
            for (int mf = 0; mf < 4; mf++) {
                const int m = wm + mf * 16;
                afr[mf][0] = __float_as_uint(As[cur][kb + tig    ][m + grp    ]);
                afr[mf][1] = __float_as_uint(As[cur][kb + tig    ][m + grp + 8]);
                afr[mf][2] = __float_as_uint(As[cur][kb + tig + 4][m + grp    ]);
                afr[mf][3] = __float_as_uint(As[cur][kb + tig + 4][m + grp + 8]);
            }
#pragma unroll
            for (int nf = 0; nf < 4; nf++) {
                const int n = wn + nf * 8;
                bfr[nf][0] = __float_as_uint(Bs[cur][kb + tig    ][n + grp]);
                bfr[nf][1] = __float_as_uint(Bs[cur][kb + tig + 4][n + grp]);
            }
#pragma unroll
            for (int mf = 0; mf < 4; mf++)
#pragma unroll
                for (int nf = 0; nf < 4; nf++)
                    mma_tf32(acc[mf][nf],
                             afr[mf][0], afr[mf][1], afr[mf][2], afr[mf][3],
                             bfr[nf][0], bfr[nf][1]);
        }

        if (pf) {
            const int nxt = cur ^ 1;
#pragma unroll
            for (int r = 0; r < 2; r++) {
                const int idx = tid + r * 256;
                const int arow = idx >> 2, ac4 = (idx & 3) * 4;
                As[nxt][ac4 + 0][arow] = to_tf32(pav[r].x);
                As[nxt][ac4 + 1][arow] = to_tf32(pav[r].y);
                As[nxt][ac4 + 2][arow] = to_tf32(pav[r].z);
                As[nxt][ac4 + 3][arow] = to_tf32(pav[r].w);
                const int brow = idx >> 5, bc4 = (idx & 31) * 4;
                float4 w;
                w.x = to_tf32(pbv[r].x); w.y = to_tf32(pbv[r].y);
                w.z = to_tf32(pbv[r].z); w.w = to_tf32(pbv[r].w);
                *(float4*)&Bs[nxt][brow][bc4] = w;
            }
        }
        __syncthreads();
    }

#pragma unroll
    for (int nf = 0; nf < 4; nf++) {
        const int col = n0 + wn + nf * 8 + tig * 2;
        const float bx = bias[col];
        const float by = bias[col + 1];
#pragma unroll
        for (int mf = 0; mf < 4; mf++) {
            const int row0 = m0 + wm + mf * 16 + grp;
            const int row1 = row0 + 8;
            float2 o0, o1;
            o0.x = acc[mf][nf][0] + bx;
            o0.y = acc[mf][nf][1] + by;
            o1.x = acc[mf][nf][2] + bx;
            o1.y = acc[mf][nf][3] + by;
            *(float2*)&Cm[(size_t)row0 * N + col] = o0;
            *(float2*)&Cm[(size_t)row1 * N + col] = o1;
        }
    }
}

// ---------------------------------------------------------------------------
// Tensor-core (tf32) flash attention with causal masking.
// Block = (qt, h, b); 8 warps; warp owns 16 q-rows of a 128-row q tile.
// ---------------------------------------------------------------------------
#define KPAD 68
#define VPAD 72
#define PPAD 68
#define ATTN_SMEM_FLOATS (64 * KPAD + 64 * VPAD + 8 * 16 * PPAD)
#define ATTN_SMEM_BYTES  (ATTN_SMEM_FLOATS * 4)

__global__ __launch_bounds__(256) void attn_tc(
    const float* __restrict__ qkv, float* __restrict__ y)
{
    extern __shared__ float sm[];
    float* Ks = sm;                    // [64][KPAD]   K^T: Ks[d*KPAD + j]
    float* Vs = Ks + 64 * KPAD;        // [64][VPAD]   Vs[j*VPAD + d]
    float* Ps = Vs + 64 * VPAD;        // [8][16][PPAD] per-warp Q/P staging

    const int tid  = threadIdx.x;
    const int wid  = tid >> 5;
    const int lane = tid & 31;
    const int grp  = lane >> 2;
    const int tig  = lane & 3;

    const int qt = blockIdx.x;
    const int h  = blockIdx.y;
    const int b  = blockIdx.z;
    const int q0 = qt * 128;
    const int wm = wid * 16;

    const float* base = qkv + (size_t)b * Td * C3 + h * 192;
    float* Pw = Ps + wid * 16 * PPAD;

    // --- stage Q rows [q0+wm, +16), scaled by 1/8, tf32, into Pw ---
#pragma unroll
    for (int i = 0; i < 8; i++) {
        const int f = i * 32 + lane;
        const int r = f >> 4, c4 = (f & 15) * 4;
        float4 v = *(const float4*)(base + (size_t)(q0 + wm + r) * C3 + c4);
        Pw[r * PPAD + c4 + 0] = to_tf32(0.125f * v.x);
        Pw[r * PPAD + c4 + 1] = to_tf32(0.125f * v.y);
        Pw[r * PPAD + c4 + 2] = to_tf32(0.125f * v.z);
        Pw[r * PPAD + c4 + 3] = to_tf32(0.125f * v.w);
    }
    __syncwarp();

    uint32_t Qa[8][4];
#pragma unroll
    for (int k = 0; k < 8; k++) {
        const int c = k * 8 + tig;
        Qa[k][0] = __float_as_uint(Pw[grp * PPAD + c]);
        Qa[k][1] = __float_as_uint(Pw[(grp + 8) * PPAD + c]);
        Qa[k][2] = __float_as_uint(Pw[grp * PPAD + c + 4]);
        Qa[k][3] = __float_as_uint(Pw[(grp + 8) * PPAD + c + 4]);
    }

    float o[8][4];
#pragma unroll
    for (int nf = 0; nf < 8; nf++)
#pragma unroll
        for (int r = 0; r < 4; r++) o[nf][r] = 0.0f;

    float m0 = -CUDART_INF_F, m1 = -CUDART_INF_F;
    float l0 = 0.0f, l1 = 0.0f;

    const int row0 = q0 + wm + grp;
    const int row1 = row0 + 8;
    const int nkt  = 2 * (qt + 1);

    for (int kt = 0; kt < nkt; kt++) {
        const int k0 = kt * 64;
        __syncthreads();   // protect Ks/Vs reuse

        // K tile transposed: Ks[d][j] = tf32(K[k0+j][d])
        {
            const int j  = tid & 63;
            const int c0 = (tid >> 6) * 16;
            const float* src = base + (size_t)(k0 + j) * C3 + 64;
#pragma unroll
            for (int i = 0; i < 4; i++) {
                float4 v = *(const float4*)(src + c0 + i * 4);
                const int d = c0 + i * 4;
                Ks[(d + 0) * KPAD + j] = to_tf32(v.x);
                Ks[(d + 1) * KPAD + j] = to_tf32(v.y);
                Ks[(d + 2) * KPAD + j] = to_tf32(v.z);
                Ks[(d + 3) * KPAD + j] = to_tf32(v.w);
            }
        }
        // V tile straight: Vs[j][d]
#pragma unroll
        for (int i = 0; i < 4; i++) {
            const int f = tid + i * 256;
            const int j = f >> 4, c4 = (f & 15) * 4;
            float4 v = *(const float4*)(base + (size_t)(k0 + j) * C3 + 128 + c4);
            float4 w;
            w.x = to_tf32(v.x); w.y = to_tf32(v.y);
            w.z = to_tf32(v.z); w.w = to_tf32(v.w);
            *(float4*)&Vs[j * VPAD + c4] = w;
        }
        __syncthreads();

        // S = Q @ K^T  (16 x 64 per warp)
        float sc[8][4];
#pragma unroll
        for (int nf = 0; nf < 8; nf++)
#pragma unroll
            for (int r = 0; r < 4; r++) sc[nf][r] = 0.0f;

#pragma unroll
        for (int k = 0; k < 8; k++) {
            const int d0 = k * 8 + tig;
#pragma unroll
            for (int nf = 0; nf < 8; nf++) {
                const int j = nf * 8 + grp;
                uint32_t b0 = __float_as_uint(Ks[d0 * KPAD + j]);
                uint32_t b1 = __float_as_uint(Ks[(d0 + 4) * KPAD + j]);
                mma_tf32(sc[nf], Qa[k][0], Qa[k][1], Qa[k][2], Qa[k][3], b0, b1);
            }
        }

        // causal mask (only last two k-tiles overlap the diagonal)
        if (k0 + 64 > q0) {
#pragma unroll
            for (int nf = 0; nf < 8; nf++) {
                const int c = k0 + nf * 8 + tig * 2;
                if (c     > row0) sc[nf][0] = -CUDART_INF_F;
                if (c + 1 > row0) sc[nf][1] = -CUDART_INF_F;
                if (c     > row1) sc[nf][2] = -CUDART_INF_F;
                if (c + 1 > row1) sc[nf][3] = -CUDART_INF_F;
            }
        }

        // online softmax
        float mt0 = -CUDART_INF_F, mt1 = -CUDART_INF_F;
#pragma unroll
        for (int nf = 0; nf < 8; nf++) {
            mt0 = fmaxf(mt0, fmaxf(sc[nf][0], sc[nf][1]));
            mt1 = fmaxf(mt1, fmaxf(sc[nf][2], sc[nf][3]));
        }
        mt0 = fmaxf(mt0, __shfl_xor_sync(0xffffffffu, mt0, 1));
        mt0 = fmaxf(mt0, __shfl_xor_sync(0xffffffffu, mt0, 2));
        mt1 = fmaxf(mt1, __shfl_xor_sync(0xffffffffu, mt1, 1));
        mt1 = fmaxf(mt1, __shfl_xor_sync(0xffffffffu, mt1, 2));

        const float mn0 = fmaxf(m0, mt0);
        const float mn1 = fmaxf(m1, mt1);
        const float corr0 = __expf(m0 - mn0);
        const float corr1 = __expf(m1 - mn1);

        float ls0 = 0.0f, ls1 = 0.0f;
#pragma unroll
        for (int nf = 0; nf < 8; nf++) {
            const float p0 = __expf(sc[nf][0] - mn0);
            const float p1 = __expf(sc[nf][1] - mn0);
            const float p2 = __expf(sc[nf][2] - mn1);
            const float p3 = __expf(sc[nf][3] - mn1);
            ls0 += p0 + p1;
            ls1 += p2 + p3;
            const int c = nf * 8 + tig * 2;
            Pw[grp * PPAD + c]           = to_tf32(p0);
            Pw[grp * PPAD + c + 1]       = to_tf32(p1);
            Pw[(grp + 8) * PPAD + c]     = to_tf32(p2);
            Pw[(grp + 8) * PPAD + c + 1] = to_tf32(p3);
        }
        ls0 += __shfl_xor_sync(0xffffffffu, ls0, 1);
        ls0 += __shfl_xor_sync(0xffffffffu, ls0, 2);
        ls1 += __shfl_xor_sync(0xffffffffu, ls1, 1);
        ls1 += __shfl_xor_sync(0xffffffffu, ls1, 2);

        l0 = l0 * corr0 + ls0;
        l1 = l1 * corr1 + ls1;
        m0 = mn0; m1 = mn1;

#pragma unroll
        for (int nf = 0; nf < 8; nf++) {
            o[nf][0] *= corr0; o[nf][1] *= corr0;
            o[nf][2] *= corr1; o[nf][3] *= corr1;
        }

        __syncwarp();   // P staging write -> read (warp-private region)

        // O += P @ V
#pragma unroll
        for (int k = 0; k < 8; k++) {
            const int c = k * 8 + tig;
            uint32_t pa0 = __float_as_uint(Pw[grp * PPAD + c]);
            uint32_t pa1 = __float_as_uint(Pw[(grp + 8) * PPAD + c]);
            uint32_t pa2 = __float_as_uint(Pw[grp * PPAD + c + 4]);
            uint32_t pa3 = __float_as_uint(Pw[(grp + 8) * PPAD + c + 4]);
#pragma unroll
            for (int nf = 0; nf < 8; nf++) {
                const int d = nf * 8 + grp;
                uint32_t b0 = __float_as_uint(Vs[(k * 8 + tig) * VPAD + d]);
                uint32_t b1 = __float_as_uint(Vs[(k * 8 + tig + 4) * VPAD + d]);
                mma_tf32(o[nf], pa0, pa1, pa2, pa3, b0, b1);
            }
        }
        __syncwarp();   // keep Pw stable until all lanes' PV reads done
    }

    const float inv0 = 1.0f / l0;
    const float inv1 = 1.0f / l1;
    float* yr = y + ((size_t)b * Td + q0 + wm) * Cd + h * HDd;
#pragma unroll
    for (int nf = 0; nf < 8; nf++) {
        const int c = nf * 8 + tig * 2;
        float2 w0, w1;
        w0.x = o[nf][0] * inv0; w0.y = o[nf][1] * inv0;
        w1.x = o[nf][2] * inv1; w1.y = o[nf][3] * inv1;
        *(float2*)&yr[(size_t)grp * Cd + c]       = w0;
        *(float2*)&yr[(size_t)(grp + 8) * Cd + c] = w1;
    }
}

// ---------------------------------------------------------------------------
extern "C" void kernel_launch(void* const* d_in, const int* in_sizes, int n_in,
                              void* d_out, int out_size)
{
    const float* x  = (const float*)d_in[0];
    const float* Wa = (const float*)d_in[1];
    const float* ba = (const float*)d_in[2];
    const float* Wp = (const float*)d_in[3];
    const float* bp = (const float*)d_in[4];
    float* out = (float*)d_out;

    float *qkv_ptr = nullptr, *y_ptr = nullptr;
    cudaGetSymbolAddress((void**)&qkv_ptr, g_qkv);
    cudaGetSymbolAddress((void**)&y_ptr, g_y);

    static bool attr_set = false;
    if (!attr_set) {
        cudaFuncSetAttribute(attn_tc, cudaFuncAttributeMaxDynamicSharedMemorySize,
                             ATTN_SMEM_BYTES);
        attr_set = true;
    }

    gemm_tf32_bias<<<dim3(C3 / GBN, (Bd * Td) / GBM), 256>>>(x, Wa, ba, qkv_ptr,
                                                             Bd * Td, C3, Cd);

    attn_tc<<<dim3(Td / 128, Hd, Bd), 256, ATTN_SMEM_BYTES>>>(qkv_ptr, y_ptr);

    gemm_tf32_bias<<<dim3(Cd / GBN, (Bd * Td) / GBM), 256>>>(y_ptr, Wp, bp, out,
                                                             Bd * Td, Cd, Cd);
}

// round 4
// speedup vs baseline: 3.6680x; 1.2943x over previous
#include <cuda_runtime.h>
#include <math_constants.h>
#include <cstdint>

// Problem constants
#define Bd   8
#define Td   1024
#define Cd   768
#define Hd   12
#define HDd  64
#define C3   2304
#define Md   (Bd * Td)   // 8192

// Scratch (__device__ globals; allocation-free rule)
__device__ float g_qkv[(size_t)Md * C3];   // [M][3C] tf32-rounded
__device__ float g_y  [(size_t)Md * Cd];   // [M][C]  tf32-rounded
__device__ float g_xr [(size_t)Md * Cd];   // x rounded
__device__ float g_war[(size_t)C3 * Cd];   // W_attn^T rounded [2304][768]
__device__ float g_wpr[(size_t)Cd * Cd];   // W_proj^T rounded [768][768]

// ---------------------------------------------------------------------------
__device__ __forceinline__ float to_tf32(float x) {
    float r;
    asm("cvt.rna.tf32.f32 %0, %1;" : "=f"(r) : "f"(x));
    return r;
}

__device__ __forceinline__ void mma_tf32(float c[4],
                                         uint32_t a0, uint32_t a1, uint32_t a2, uint32_t a3,
                                         uint32_t b0, uint32_t b1) {
    asm volatile(
        "mma.sync.aligned.m16n8k8.row.col.f32.tf32.tf32.f32 "
        "{%0,%1,%2,%3}, {%4,%5,%6,%7}, {%8,%9}, {%0,%1,%2,%3};"
        : "+f"(c[0]), "+f"(c[1]), "+f"(c[2]), "+f"(c[3])
        : "r"(a0), "r"(a1), "r"(a2), "r"(a3), "r"(b0), "r"(b1));
}

__device__ __forceinline__ uint32_t sptr(const void* p) {
    return (uint32_t)__cvta_generic_to_shared(p);
}

__device__ __forceinline__ void ldsm4(uint32_t& r0, uint32_t& r1,
                                      uint32_t& r2, uint32_t& r3, uint32_t addr) {
    asm volatile("ldmatrix.sync.aligned.m8n8.x4.shared.b16 {%0,%1,%2,%3}, [%4];"
                 : "=r"(r0), "=r"(r1), "=r"(r2), "=r"(r3) : "r"(addr));
}

__device__ __forceinline__ void cp16(uint32_t dst, const void* src) {
    asm volatile("cp.async.cg.shared.global [%0], [%1], 16;\n" :: "r"(dst), "l"(src));
}
__device__ __forceinline__ void cp_commit() {
    asm volatile("cp.async.commit_group;\n");
}
template <int N>
__device__ __forceinline__ void cp_wait() {
    asm volatile("cp.async.wait_group %0;\n" :: "n"(N));
}

// ---------------------------------------------------------------------------
// Prep kernels
// ---------------------------------------------------------------------------
__global__ void round4_kernel(const float4* __restrict__ in, float4* __restrict__ out, int n4) {
    int i = blockIdx.x * blockDim.x + threadIdx.x;
    if (i < n4) {
        float4 v = in[i];
        v.x = to_tf32(v.x); v.y = to_tf32(v.y);
        v.z = to_tf32(v.z); v.w = to_tf32(v.w);
        out[i] = v;
    }
}

// in [R][C] -> out [C][R], tf32-rounded. Block (32,8), grid (C/32, R/32).
__global__ void transpose_round(const float* __restrict__ in, float* __restrict__ out,
                                int R, int C) {
    __shared__ float t[32][33];
    const int bx = blockIdx.x * 32;   // col base
    const int by = blockIdx.y * 32;   // row base
#pragma unroll
    for (int i = 0; i < 4; i++) {
        int y = by + threadIdx.y + i * 8;
        t[threadIdx.y + i * 8][threadIdx.x] = to_tf32(in[(size_t)y * C + bx + threadIdx.x]);
    }
    __syncthreads();
#pragma unroll
    for (int i = 0; i < 4; i++) {
        int oy = bx + threadIdx.y + i * 8;     // out row = original col
        out[(size_t)oy * R + by + threadIdx.x] = t[threadIdx.x][threadIdx.y + i * 8];
    }
}

// ---------------------------------------------------------------------------
// TF32 TN GEMM + bias: C[M,N] = A[M,K] @ BT[N,K]^T + bias[N]
// 128x128x16 tile, 8 warps, cp.async 3-stage, ldmatrix fragments.
// ---------------------------------------------------------------------------
#define GBK   16
#define KROW  20                  // padded row (words): 5m mod 8 distinct phases
#define STAGES 3
#define TILE_FLOATS (128 * KROW)
#define GEMM_SMEM_BYTES (STAGES * TILE_FLOATS * 2 * 4)

template <bool ROUND_OUT>
__global__ __launch_bounds__(256) void gemm_tn(
    const float* __restrict__ A,    // [M][K]
    const float* __restrict__ BT,   // [N][K]
    const float* __restrict__ bias,
    float* __restrict__ Cm,
    int M, int N, int K)
{
    extern __shared__ float sm[];
    float* As = sm;                          // [STAGES][128][KROW]
    float* Bs = sm + STAGES * TILE_FLOATS;

    const int tid  = threadIdx.x;
    const int wid  = tid >> 5;
    const int lane = tid & 31;
    const int grp  = lane >> 2;
    const int tig  = lane & 3;

    const int m0 = blockIdx.y * 128;
    const int n0 = blockIdx.x * 128;
    const int wm = (wid & 1) * 64;
    const int wn = (wid >> 1) * 32;

    // ldmatrix lane address components
    const int a_off = ((lane >> 3) & 1) * 8 + (lane & 7);
    const int a_k   = (lane >> 4) * 4;
    const int b_off = (lane >> 4) * 8 + (lane & 7);
    const int b_k   = ((lane >> 3) & 1) * 4;

    // cp.async staging map: 512 chunks/operand, 2 per thread
    const int s_row0 = tid >> 2;              // 0..63
    const int s_c    = (tid & 3) * 4;         // 0,4,8,12
    const uint32_t As_s = sptr(As);
    const uint32_t Bs_s = sptr(Bs);

    float acc[4][4][4];
#pragma unroll
    for (int i = 0; i < 4; i++)
#pragma unroll
        for (int j = 0; j < 4; j++)
#pragma unroll
            for (int r = 0; r < 4; r++) acc[i][j][r] = 0.0f;

    const int nk = K / GBK;

    // issue stage for k-iter t
    auto issue = [&](int t) {
        const int st = t % STAGES;
        const int k0 = t * GBK;
        const uint32_t ab = As_s + (uint32_t)(st * TILE_FLOATS) * 4u;
        const uint32_t bb = Bs_s + (uint32_t)(st * TILE_FLOATS) * 4u;
#pragma unroll
        for (int r = 0; r < 2; r++) {
            const int row = s_row0 + r * 64;
            cp16(ab + (uint32_t)(row * KROW + s_c) * 4u,
                 &A[(size_t)(m0 + row) * K + k0 + s_c]);
            cp16(bb + (uint32_t)(row * KROW + s_c) * 4u,
                 &BT[(size_t)(n0 + row) * K + k0 + s_c]);
        }
    };

#pragma unroll
    for (int t = 0; t < STAGES - 1; t++) {
        issue(t);
        cp_commit();
    }

    for (int t = 0; t < nk; t++) {
        const int pre = t + STAGES - 1;
        if (pre < nk) issue(pre);
        cp_commit();
        cp_wait<STAGES - 1>();   // groups 0..t complete -> stage t ready
        __syncthreads();

        const int st = t % STAGES;
        const uint32_t ab = As_s + (uint32_t)(st * TILE_FLOATS) * 4u;
        const uint32_t bb = Bs_s + (uint32_t)(st * TILE_FLOATS) * 4u;

#pragma unroll
        for (int ks = 0; ks < 2; ks++) {
            const int kb = ks * 8;
            uint32_t a[4][4];
            uint32_t b[4][2];
#pragma unroll
            for (int mf = 0; mf < 4; mf++) {
                ldsm4(a[mf][0], a[mf][1], a[mf][2], a[mf][3],
                      ab + (uint32_t)((wm + mf * 16 + a_off) * KROW + kb + a_k) * 4u);
            }
#pragma unroll
            for (int p = 0; p < 2; p++) {
                ldsm4(b[2 * p][0], b[2 * p][1], b[2 * p + 1][0], b[2 * p + 1][1],
                      bb + (uint32_t)((wn + p * 16 + b_off) * KROW + kb + b_k) * 4u);
            }
#pragma unroll
            for (int mf = 0; mf < 4; mf++)
#pragma unroll
                for (int nf = 0; nf < 4; nf++)
                    mma_tf32(acc[mf][nf],
                             a[mf][0], a[mf][1], a[mf][2], a[mf][3],
                             b[nf][0], b[nf][1]);
        }
        __syncthreads();
    }

    // epilogue
#pragma unroll
    for (int nf = 0; nf < 4; nf++) {
        const int col = n0 + wn + nf * 8 + tig * 2;
        const float bx = bias[col];
        const float by = bias[col + 1];
#pragma unroll
        for (int mf = 0; mf < 4; mf++) {
            const int row0 = m0 + wm + mf * 16 + grp;
            const int row1 = row0 + 8;
            float2 o0, o1;
            o0.x = acc[mf][nf][0] + bx;
            o0.y = acc[mf][nf][1] + by;
            o1.x = acc[mf][nf][2] + bx;
            o1.y = acc[mf][nf][3] + by;
            if (ROUND_OUT) {
                o0.x = to_tf32(o0.x); o0.y = to_tf32(o0.y);
                o1.x = to_tf32(o1.x); o1.y = to_tf32(o1.y);
            }
            *(float2*)&Cm[(size_t)row0 * N + col] = o0;
            *(float2*)&Cm[(size_t)row1 * N + col] = o1;
        }
    }
}

// ---------------------------------------------------------------------------
// Tensor-core flash attention, ldmatrix fragments everywhere.
// Block (qt, h, b), 8 warps, warp owns 16 q-rows of a 128-row tile.
// ---------------------------------------------------------------------------
#define APAD 68
#define ATTN_SMEM_FLOATS (64 * APAD + 64 * APAD + 8 * 16 * APAD)
#define ATTN_SMEM_BYTES  (ATTN_SMEM_FLOATS * 4)

__global__ __launch_bounds__(256) void attn_tc(
    const float* __restrict__ qkv, float* __restrict__ y)
{
    extern __shared__ float sm[];
    float* Ks = sm;                 // [64][APAD]  K rows (n=j major, k=d minor)
    float* Vs = Ks + 64 * APAD;     // [64][APAD]  V transposed (n=d major, k=j minor)
    float* Ps = Vs + 64 * APAD;     // [8][16][APAD] per-warp Q/P staging

    const int tid  = threadIdx.x;
    const int wid  = tid >> 5;
    const int lane = tid & 31;
    const int grp  = lane >> 2;
    const int tig  = lane & 3;

    const int qt = blockIdx.x;
    const int h  = blockIdx.y;
    const int b  = blockIdx.z;
    const int q0 = qt * 128;
    const int wm = wid * 16;

    const float* base = qkv + (size_t)b * Td * C3 + h * 192;
    float* Pw = Ps + wid * 16 * APAD;

    const int a_off = ((lane >> 3) & 1) * 8 + (lane & 7);
    const int a_k   = (lane >> 4) * 4;
    const int b_off = (lane >> 4) * 8 + (lane & 7);
    const int b_k   = ((lane >> 3) & 1) * 4;

    // stage Q (pre-rounded tf32; *0.125 is exact)
#pragma unroll
    for (int i = 0; i < 8; i++) {
        const int f = i * 32 + lane;
        const int r = f >> 4, c4 = (f & 15) * 4;
        float4 v = *(const float4*)(base + (size_t)(q0 + wm + r) * C3 + c4);
        v.x *= 0.125f; v.y *= 0.125f; v.z *= 0.125f; v.w *= 0.125f;
        *(float4*)&Pw[r * APAD + c4] = v;
    }
    __syncwarp();

    uint32_t Qa[8][4];
#pragma unroll
    for (int k = 0; k < 8; k++)
        ldsm4(Qa[k][0], Qa[k][1], Qa[k][2], Qa[k][3],
              sptr(&Pw[a_off * APAD + k * 8 + a_k]));

    float o[8][4];
#pragma unroll
    for (int nf = 0; nf < 8; nf++)
#pragma unroll
        for (int r = 0; r < 4; r++) o[nf][r] = 0.0f;

    float mx0 = -CUDART_INF_F, mx1 = -CUDART_INF_F;
    float l0 = 0.0f, l1 = 0.0f;

    const int row0 = q0 + wm + grp;
    const int row1 = row0 + 8;
    const int nkt  = 2 * (qt + 1);

    for (int kt = 0; kt < nkt; kt++) {
        const int k0 = kt * 64;
        __syncthreads();

        // K tile: natural rows [j][d]
#pragma unroll
        for (int i = 0; i < 4; i++) {
            const int idx = tid + i * 256;
            const int j = idx >> 4, c4 = (idx & 15) * 4;
            *(float4*)&Ks[j * APAD + c4] =
                *(const float4*)(base + (size_t)(k0 + j) * C3 + 64 + c4);
        }
        // V tile transposed: Vs[d][j] (coalesced scalar LDG, float4 STS)
        {
            const int d  = tid & 63;
            const int jg = tid >> 6;   // 0..3
#pragma unroll
            for (int i = 0; i < 4; i++) {
                const int j = jg * 16 + i * 4;
                const float* s = base + (size_t)(k0 + j) * C3 + 128 + d;
                float4 w;
                w.x = s[0];
                w.y = s[C3];
                w.z = s[2 * C3];
                w.w = s[3 * C3];
                *(float4*)&Vs[d * APAD + j] = w;
            }
        }
        __syncthreads();

        // S = Q @ K^T
        float sc[8][4];
#pragma unroll
        for (int nf = 0; nf < 8; nf++)
#pragma unroll
            for (int r = 0; r < 4; r++) sc[nf][r] = 0.0f;

#pragma unroll
        for (int k = 0; k < 8; k++) {
            const int d0 = k * 8;
            uint32_t bf[8][2];
#pragma unroll
            for (int p = 0; p < 4; p++)
                ldsm4(bf[2 * p][0], bf[2 * p][1], bf[2 * p + 1][0], bf[2 * p + 1][1],
                      sptr(&Ks[(p * 16 + b_off) * APAD + d0 + b_k]));
#pragma unroll
            for (int nf = 0; nf < 8; nf++)
                mma_tf32(sc[nf], Qa[k][0], Qa[k][1], Qa[k][2], Qa[k][3],
                         bf[nf][0], bf[nf][1]);
        }

        // causal mask
        if (k0 + 64 > q0) {
#pragma unroll
            for (int nf = 0; nf < 8; nf++) {
                const int c = k0 + nf * 8 + tig * 2;
                if (c     > row0) sc[nf][0] = -CUDART_INF_F;
                if (c + 1 > row0) sc[nf][1] = -CUDART_INF_F;
                if (c     > row1) sc[nf][2] = -CUDART_INF_F;
                if (c + 1 > row1) sc[nf][3] = -CUDART_INF_F;
            }
        }

        // online softmax
        float mt0 = -CUDART_INF_F, mt1 = -CUDART_INF_F;
#pragma unroll
        for (int nf = 0; nf < 8; nf++) {
            mt0 = fmaxf(mt0, fmaxf(sc[nf][0], sc[nf][1]));
            mt1 = fmaxf(mt1, fmaxf(sc[nf][2], sc[nf][3]));
        }
        mt0 = fmaxf(mt0, __shfl_xor_sync(0xffffffffu, mt0, 1));
        mt0 = fmaxf(mt0, __shfl_xor_sync(0xffffffffu, mt0, 2));
        mt1 = fmaxf(mt1, __shfl_xor_sync(0xffffffffu, mt1, 1));
        mt1 = fmaxf(mt1, __shfl_xor_sync(0xffffffffu, mt1, 2));

        const float mn0 = fmaxf(mx0, mt0);
        const float mn1 = fmaxf(mx1, mt1);
        const float corr0 = __expf(mx0 - mn0);
        const float corr1 = __expf(mx1 - mn1);

        float ls0 = 0.0f, ls1 = 0.0f;
#pragma unroll
        for (int nf = 0; nf < 8; nf++) {
            const float p0 = __expf(sc[nf][0] - mn0);
            const float p1 = __expf(sc[nf][1] - mn0);
            const float p2 = __expf(sc[nf][2] - mn1);
            const float p3 = __expf(sc[nf][3] - mn1);
            ls0 += p0 + p1;
            ls1 += p2 + p3;
            const int c = nf * 8 + tig * 2;
            Pw[grp * APAD + c]           = to_tf32(p0);
            Pw[grp * APAD + c + 1]       = to_tf32(p1);
            Pw[(grp + 8) * APAD + c]     = to_tf32(p2);
            Pw[(grp + 8) * APAD + c + 1] = to_tf32(p3);
        }
        ls0 += __shfl_xor_sync(0xffffffffu, ls0, 1);
        ls0 += __shfl_xor_sync(0xffffffffu, ls0, 2);
        ls1 += __shfl_xor_sync(0xffffffffu, ls1, 1);
        ls1 += __shfl_xor_sync(0xffffffffu, ls1, 2);

        l0 = l0 * corr0 + ls0;
        l1 = l1 * corr1 + ls1;
        mx0 = mn0; mx1 = mn1;

#pragma unroll
        for (int nf = 0; nf < 8; nf++) {
            o[nf][0] *= corr0; o[nf][1] *= corr0;
            o[nf][2] *= corr1; o[nf][3] *= corr1;
        }

        __syncwarp();

        // O += P @ V
#pragma unroll
        for (int k = 0; k < 8; k++) {
            const int kb = k * 8;
            uint32_t pa[4];
            ldsm4(pa[0], pa[1], pa[2], pa[3],
                  sptr(&Pw[a_off * APAD + kb + a_k]));
            uint32_t bf[8][2];
#pragma unroll
            for (int p = 0; p < 4; p++)
                ldsm4(bf[2 * p][0], bf[2 * p][1], bf[2 * p + 1][0], bf[2 * p + 1][1],
                      sptr(&Vs[(p * 16 + b_off) * APAD + kb + b_k]));
#pragma unroll
            for (int nf = 0; nf < 8; nf++)
                mma_tf32(o[nf], pa[0], pa[1], pa[2], pa[3], bf[nf][0], bf[nf][1]);
        }
        __syncwarp();
    }

    const float inv0 = 1.0f / l0;
    const float inv1 = 1.0f / l1;
    float* yr = y + ((size_t)b * Td + q0 + wm) * Cd + h * HDd;
#pragma unroll
    for (int nf = 0; nf < 8; nf++) {
        const int c = nf * 8 + tig * 2;
        float2 w0, w1;
        w0.x = to_tf32(o[nf][0] * inv0); w0.y = to_tf32(o[nf][1] * inv0);
        w1.x = to_tf32(o[nf][2] * inv1); w1.y = to_tf32(o[nf][3] * inv1);
        *(float2*)&yr[(size_t)grp * Cd + c]       = w0;
        *(float2*)&yr[(size_t)(grp + 8) * Cd + c] = w1;
    }
}

// ---------------------------------------------------------------------------
extern "C" void kernel_launch(void* const* d_in, const int* in_sizes, int n_in,
                              void* d_out, int out_size)
{
    const float* x  = (const float*)d_in[0];
    const float* Wa = (const float*)d_in[1];
    const float* ba = (const float*)d_in[2];
    const float* Wp = (const float*)d_in[3];
    const float* bp = (const float*)d_in[4];
    float* out = (float*)d_out;

    float *qkv_p, *y_p, *xr_p, *war_p, *wpr_p;
    cudaGetSymbolAddress((void**)&qkv_p, g_qkv);
    cudaGetSymbolAddress((void**)&y_p,   g_y);
    cudaGetSymbolAddress((void**)&xr_p,  g_xr);
    cudaGetSymbolAddress((void**)&war_p, g_war);
    cudaGetSymbolAddress((void**)&wpr_p, g_wpr);

    cudaFuncSetAttribute(gemm_tn<true>,  cudaFuncAttributeMaxDynamicSharedMemorySize, GEMM_SMEM_BYTES);
    cudaFuncSetAttribute(gemm_tn<false>, cudaFuncAttributeMaxDynamicSharedMemorySize, GEMM_SMEM_BYTES);
    cudaFuncSetAttribute(attn_tc,        cudaFuncAttributeMaxDynamicSharedMemorySize, ATTN_SMEM_BYTES);

    // prep: round x; round+transpose weights
    round4_kernel<<<(Md * Cd / 4 + 255) / 256, 256>>>((const float4*)x, (float4*)xr_p, Md * Cd / 4);
    transpose_round<<<dim3(C3 / 32, Cd / 32), dim3(32, 8)>>>(Wa, war_p, Cd, C3);
    transpose_round<<<dim3(Cd / 32, Cd / 32), dim3(32, 8)>>>(Wp, wpr_p, Cd, Cd);

    // 1) qkv = x @ W_attn + b_attn  (rounded output)
    gemm_tn<true><<<dim3(C3 / 128, Md / 128), 256, GEMM_SMEM_BYTES>>>(
        xr_p, war_p, ba, qkv_p, Md, C3, Cd);

    // 2) attention
    attn_tc<<<dim3(Td / 128, Hd, Bd), 256, ATTN_SMEM_BYTES>>>(qkv_p, y_p);

    // 3) out = y @ W_proj + b_proj  (full fp32 output)
    gemm_tn<false><<<dim3(Cd / 128, Md / 128), 256, GEMM_SMEM_BYTES>>>(
        y_p, wpr_p, bp, out, Md, Cd, Cd);
}

// round 5
// speedup vs baseline: 4.1981x; 1.1445x over previous
#include <cuda_runtime.h>
#include <math_constants.h>
#include <cstdint>

// Problem constants
#define Bd   8
#define Td   1024
#define Cd   768
#define Hd   12
#define HDd  64
#define C3   2304
#define Md   (Bd * Td)   // 8192

// Scratch (__device__ globals; allocation-free rule)
__device__ float g_qkv[(size_t)Md * C3];
__device__ float g_y  [(size_t)Md * Cd];
__device__ float g_xr [(size_t)Md * Cd];
__device__ float g_war[(size_t)C3 * Cd];
__device__ float g_wpr[(size_t)Cd * Cd];

// ---------------------------------------------------------------------------
__device__ __forceinline__ float to_tf32(float x) {
    float r;
    asm("cvt.rna.tf32.f32 %0, %1;" : "=f"(r) : "f"(x));
    return r;
}

__device__ __forceinline__ void mma_tf32(float c[4],
                                         uint32_t a0, uint32_t a1, uint32_t a2, uint32_t a3,
                                         uint32_t b0, uint32_t b1) {
    asm volatile(
        "mma.sync.aligned.m16n8k8.row.col.f32.tf32.tf32.f32 "
        "{%0,%1,%2,%3}, {%4,%5,%6,%7}, {%8,%9}, {%0,%1,%2,%3};"
        : "+f"(c[0]), "+f"(c[1]), "+f"(c[2]), "+f"(c[3])
        : "r"(a0), "r"(a1), "r"(a2), "r"(a3), "r"(b0), "r"(b1));
}

__device__ __forceinline__ uint32_t sptr(const void* p) {
    return (uint32_t)__cvta_generic_to_shared(p);
}

__device__ __forceinline__ void ldsm4(uint32_t& r0, uint32_t& r1,
                                      uint32_t& r2, uint32_t& r3, uint32_t addr) {
    asm volatile("ldmatrix.sync.aligned.m8n8.x4.shared.b16 {%0,%1,%2,%3}, [%4];"
                 : "=r"(r0), "=r"(r1), "=r"(r2), "=r"(r3) : "r"(addr));
}

__device__ __forceinline__ void cp16(uint32_t dst, const void* src) {
    asm volatile("cp.async.cg.shared.global [%0], [%1], 16;\n" :: "r"(dst), "l"(src));
}
__device__ __forceinline__ void cp_commit() {
    asm volatile("cp.async.commit_group;\n");
}
template <int N>
__device__ __forceinline__ void cp_wait() {
    asm volatile("cp.async.wait_group %0;\n" :: "n"(N));
}

// GEMM tile swizzle: rows of 16 floats, packed. word w in [0,16).
// quad index (addr/16B) mod 8 distinct over any 8 consecutive rows.
__device__ __forceinline__ uint32_t gswz(int r, int w) {
    return (uint32_t)(r * 16 + (((w >> 2) ^ ((r >> 1) & 3)) << 2) + (w & 3));
}

// ---------------------------------------------------------------------------
// Prep kernels
// ---------------------------------------------------------------------------
__global__ void round4_kernel(const float4* __restrict__ in, float4* __restrict__ out, int n4) {
    int i = blockIdx.x * blockDim.x + threadIdx.x;
    if (i < n4) {
        float4 v = in[i];
        v.x = to_tf32(v.x); v.y = to_tf32(v.y);
        v.z = to_tf32(v.z); v.w = to_tf32(v.w);
        out[i] = v;
    }
}

__global__ void transpose_round(const float* __restrict__ in, float* __restrict__ out,
                                int R, int C) {
    __shared__ float t[32][33];
    const int bx = blockIdx.x * 32;
    const int by = blockIdx.y * 32;
#pragma unroll
    for (int i = 0; i < 4; i++) {
        int y = by + threadIdx.y + i * 8;
        t[threadIdx.y + i * 8][threadIdx.x] = to_tf32(in[(size_t)y * C + bx + threadIdx.x]);
    }
    __syncthreads();
#pragma unroll
    for (int i = 0; i < 4; i++) {
        int oy = bx + threadIdx.y + i * 8;
        out[(size_t)oy * R + by + threadIdx.x] = t[threadIdx.x][threadIdx.y + i * 8];
    }
}

// ---------------------------------------------------------------------------
// TF32 TN GEMM + bias: C[M,N] = A[M,K] @ BT[N,K]^T + bias[N]
// 128x128x16 tile, 8 warps, cp.async 4-stage, swizzled smem, 2 CTAs/SM.
// ---------------------------------------------------------------------------
#define GBK   16
#define STAGES 4
#define TILE_FLOATS (128 * 16)
#define GEMM_SMEM_BYTES (STAGES * TILE_FLOATS * 2 * 4)   // 64 KB

template <bool ROUND_OUT>
__global__ __launch_bounds__(256, 2) void gemm_tn(
    const float* __restrict__ A,    // [M][K]
    const float* __restrict__ BT,   // [N][K]
    const float* __restrict__ bias,
    float* __restrict__ Cm,
    int M, int N, int K)
{
    extern __shared__ float sm[];
    float* As = sm;                          // [STAGES][128*16] swizzled
    float* Bs = sm + STAGES * TILE_FLOATS;

    const int tid  = threadIdx.x;
    const int wid  = tid >> 5;
    const int lane = tid & 31;
    const int grp  = lane >> 2;
    const int tig  = lane & 3;

    const int m0 = blockIdx.y * 128;
    const int n0 = blockIdx.x * 128;
    const int wm = (wid & 1) * 64;
    const int wn = (wid >> 1) * 32;

    const int a_off = ((lane >> 3) & 1) * 8 + (lane & 7);
    const int a_k   = (lane >> 4) * 4;
    const int b_off = (lane >> 4) * 8 + (lane & 7);
    const int b_k   = ((lane >> 3) & 1) * 4;

    const int s_row0 = tid >> 2;              // 0..63
    const int s_c    = (tid & 3) * 4;         // 0,4,8,12
    const uint32_t As_s = sptr(As);
    const uint32_t Bs_s = sptr(Bs);

    float acc[4][4][4];
#pragma unroll
    for (int i = 0; i < 4; i++)
#pragma unroll
        for (int j = 0; j < 4; j++)
#pragma unroll
            for (int r = 0; r < 4; r++) acc[i][j][r] = 0.0f;

    const int nk = K / GBK;

    auto issue = [&](int t) {
        const int st = t % STAGES;
        const int k0 = t * GBK;
        const uint32_t ab = As_s + (uint32_t)(st * TILE_FLOATS) * 4u;
        const uint32_t bb = Bs_s + (uint32_t)(st * TILE_FLOATS) * 4u;
#pragma unroll
        for (int r = 0; r < 2; r++) {
            const int row = s_row0 + r * 64;
            const uint32_t so = gswz(row, s_c) * 4u;
            cp16(ab + so, &A [(size_t)(m0 + row) * K + k0 + s_c]);
            cp16(bb + so, &BT[(size_t)(n0 + row) * K + k0 + s_c]);
        }
    };

#pragma unroll
    for (int t = 0; t < STAGES - 1; t++) {
        issue(t);
        cp_commit();
    }

    for (int t = 0; t < nk; t++) {
        const int pre = t + STAGES - 1;
        if (pre < nk) issue(pre);
        cp_commit();
        cp_wait<STAGES - 1>();
        __syncthreads();

        const int st = t % STAGES;
        const uint32_t ab = As_s + (uint32_t)(st * TILE_FLOATS) * 4u;
        const uint32_t bb = Bs_s + (uint32_t)(st * TILE_FLOATS) * 4u;

#pragma unroll
        for (int ks = 0; ks < 2; ks++) {
            const int kb = ks * 8;
            uint32_t a[4][4];
            uint32_t b[4][2];
#pragma unroll
            for (int mf = 0; mf < 4; mf++)
                ldsm4(a[mf][0], a[mf][1], a[mf][2], a[mf][3],
                      ab + gswz(wm + mf * 16 + a_off, kb + a_k) * 4u);
#pragma unroll
            for (int p = 0; p < 2; p++)
                ldsm4(b[2 * p][0], b[2 * p][1], b[2 * p + 1][0], b[2 * p + 1][1],
                      bb + gswz(wn + p * 16 + b_off, kb + b_k) * 4u);
#pragma unroll
            for (int mf = 0; mf < 4; mf++)
#pragma unroll
                for (int nf = 0; nf < 4; nf++)
                    mma_tf32(acc[mf][nf],
                             a[mf][0], a[mf][1], a[mf][2], a[mf][3],
                             b[nf][0], b[nf][1]);
        }
        __syncthreads();
    }

#pragma unroll
    for (int nf = 0; nf < 4; nf++) {
        const int col = n0 + wn + nf * 8 + tig * 2;
        const float bx = bias[col];
        const float by = bias[col + 1];
#pragma unroll
        for (int mf = 0; mf < 4; mf++) {
            const int row0 = m0 + wm + mf * 16 + grp;
            const int row1 = row0 + 8;
            float2 o0, o1;
            o0.x = acc[mf][nf][0] + bx;
            o0.y = acc[mf][nf][1] + by;
            o1.x = acc[mf][nf][2] + bx;
            o1.y = acc[mf][nf][3] + by;
            if (ROUND_OUT) {
                o0.x = to_tf32(o0.x); o0.y = to_tf32(o0.y);
                o1.x = to_tf32(o1.x); o1.y = to_tf32(o1.y);
            }
            *(float2*)&Cm[(size_t)row0 * N + col] = o0;
            *(float2*)&Cm[(size_t)row1 * N + col] = o1;
        }
    }
}

// ---------------------------------------------------------------------------
// Tensor-core flash attention (unchanged from R4 — known correct).
// ---------------------------------------------------------------------------
#define APAD 68
#define ATTN_SMEM_FLOATS (64 * APAD + 64 * APAD + 8 * 16 * APAD)
#define ATTN_SMEM_BYTES  (ATTN_SMEM_FLOATS * 4)

__global__ __launch_bounds__(256) void attn_tc(
    const float* __restrict__ qkv, float* __restrict__ y)
{
    extern __shared__ float sm[];
    float* Ks = sm;
    float* Vs = Ks + 64 * APAD;
    float* Ps = Vs + 64 * APAD;

    const int tid  = threadIdx.x;
    const int wid  = tid >> 5;
    const int lane = tid & 31;
    const int grp  = lane >> 2;
    const int tig  = lane & 3;

    const int qt = blockIdx.x;
    const int h  = blockIdx.y;
    const int b  = blockIdx.z;
    const int q0 = qt * 128;
    const int wm = wid * 16;

    const float* base = qkv + (size_t)b * Td * C3 + h * 192;
    float* Pw = Ps + wid * 16 * APAD;

    const int a_off = ((lane >> 3) & 1) * 8 + (lane & 7);
    const int a_k   = (lane >> 4) * 4;
    const int b_off = (lane >> 4) * 8 + (lane & 7);
    const int b_k   = ((lane >> 3) & 1) * 4;

#pragma unroll
    for (int i = 0; i < 8; i++) {
        const int f = i * 32 + lane;
        const int r = f >> 4, c4 = (f & 15) * 4;
        float4 v = *(const float4*)(base + (size_t)(q0 + wm + r) * C3 + c4);
        v.x *= 0.125f; v.y *= 0.125f; v.z *= 0.125f; v.w *= 0.125f;
        *(float4*)&Pw[r * APAD + c4] = v;
    }
    __syncwarp();

    uint32_t Qa[8][4];
#pragma unroll
    for (int k = 0; k < 8; k++)
        ldsm4(Qa[k][0], Qa[k][1], Qa[k][2], Qa[k][3],
              sptr(&Pw[a_off * APAD + k * 8 + a_k]));

    float o[8][4];
#pragma unroll
    for (int nf = 0; nf < 8; nf++)
#pragma unroll
        for (int r = 0; r < 4; r++) o[nf][r] = 0.0f;

    float mx0 = -CUDART_INF_F, mx1 = -CUDART_INF_F;
    float l0 = 0.0f, l1 = 0.0f;

    const int row0 = q0 + wm + grp;
    const int row1 = row0 + 8;
    const int nkt  = 2 * (qt + 1);

    for (int kt = 0; kt < nkt; kt++) {
        const int k0 = kt * 64;
        __syncthreads();

#pragma unroll
        for (int i = 0; i < 4; i++) {
            const int idx = tid + i * 256;
            const int j = idx >> 4, c4 = (idx & 15) * 4;
            *(float4*)&Ks[j * APAD + c4] =
                *(const float4*)(base + (size_t)(k0 + j) * C3 + 64 + c4);
        }
        {
            const int d  = tid & 63;
            const int jg = tid >> 6;
#pragma unroll
            for (int i = 0; i < 4; i++) {
                const int j = jg * 16 + i * 4;
                const float* s = base + (size_t)(k0 + j) * C3 + 128 + d;
                float4 w;
                w.x = s[0];
                w.y = s[C3];
                w.z = s[2 * C3];
                w.w = s[3 * C3];
                *(float4*)&Vs[d * APAD + j] = w;
            }
        }
        __syncthreads();

        float sc[8][4];
#pragma unroll
        for (int nf = 0; nf < 8; nf++)
#pragma unroll
            for (int r = 0; r < 4; r++) sc[nf][r] = 0.0f;

#pragma unroll
        for (int k = 0; k < 8; k++) {
            const int d0 = k * 8;
            uint32_t bf[8][2];
#pragma unroll
            for (int p = 0; p < 4; p++)
                ldsm4(bf[2 * p][0], bf[2 * p][1], bf[2 * p + 1][0], bf[2 * p + 1][1],
                      sptr(&Ks[(p * 16 + b_off) * APAD + d0 + b_k]));
#pragma unroll
            for (int nf = 0; nf < 8; nf++)
                mma_tf32(sc[nf], Qa[k][0], Qa[k][1], Qa[k][2], Qa[k][3],
                         bf[nf][0], bf[nf][1]);
        }

        if (k0 + 64 > q0) {
#pragma unroll
            for (int nf = 0; nf < 8; nf++) {
                const int c = k0 + nf * 8 + tig * 2;
                if (c     > row0) sc[nf][0] = -CUDART_INF_F;
                if (c + 1 > row0) sc[nf][1] = -CUDART_INF_F;
                if (c     > row1) sc[nf][2] = -CUDART_INF_F;
                if (c + 1 > row1) sc[nf][3] = -CUDART_INF_F;
            }
        }

        float mt0 = -CUDART_INF_F, mt1 = -CUDART_INF_F;
#pragma unroll
        for (int nf = 0; nf < 8; nf++) {
            mt0 = fmaxf(mt0, fmaxf(sc[nf][0], sc[nf][1]));
            mt1 = fmaxf(mt1, fmaxf(sc[nf][2], sc[nf][3]));
        }
        mt0 = fmaxf(mt0, __shfl_xor_sync(0xffffffffu, mt0, 1));
        mt0 = fmaxf(mt0, __shfl_xor_sync(0xffffffffu, mt0, 2));
        mt1 = fmaxf(mt1, __shfl_xor_sync(0xffffffffu, mt1, 1));
        mt1 = fmaxf(mt1, __shfl_xor_sync(0xffffffffu, mt1, 2));

        const float mn0 = fmaxf(mx0, mt0);
        const float mn1 = fmaxf(mx1, mt1);
        const float corr0 = __expf(mx0 - mn0);
        const float corr1 = __expf(mx1 - mn1);

        float ls0 = 0.0f, ls1 = 0.0f;
#pragma unroll
        for (int nf = 0; nf < 8; nf++) {
            const float p0 = __expf(sc[nf][0] - mn0);
            const float p1 = __expf(sc[nf][1] - mn0);
            const float p2 = __expf(sc[nf][2] - mn1);
            const float p3 = __expf(sc[nf][3] - mn1);
            ls0 += p0 + p1;
            ls1 += p2 + p3;
            const int c = nf * 8 + tig * 2;
            Pw[grp * APAD + c]           = to_tf32(p0);
            Pw[grp * APAD + c + 1]       = to_tf32(p1);
            Pw[(grp + 8) * APAD + c]     = to_tf32(p2);
            Pw[(grp + 8) * APAD + c + 1] = to_tf32(p3);
        }
        ls0 += __shfl_xor_sync(0xffffffffu, ls0, 1);
        ls0 += __shfl_xor_sync(0xffffffffu, ls0, 2);
        ls1 += __shfl_xor_sync(0xffffffffu, ls1, 1);
        ls1 += __shfl_xor_sync(0xffffffffu, ls1, 2);

        l0 = l0 * corr0 + ls0;
        l1 = l1 * corr1 + ls1;
        mx0 = mn0; mx1 = mn1;

#pragma unroll
        for (int nf = 0; nf < 8; nf++) {
            o[nf][0] *= corr0; o[nf][1] *= corr0;
            o[nf][2] *= corr1; o[nf][3] *= corr1;
        }

        __syncwarp();

#pragma unroll
        for (int k = 0; k < 8; k++) {
            const int kb = k * 8;
            uint32_t pa[4];
            ldsm4(pa[0], pa[1], pa[2], pa[3],
                  sptr(&Pw[a_off * APAD + kb + a_k]));
            uint32_t bf[8][2];
#pragma unroll
            for (int p = 0; p < 4; p++)
                ldsm4(bf[2 * p][0], bf[2 * p][1], bf[2 * p + 1][0], bf[2 * p + 1][1],
                      sptr(&Vs[(p * 16 + b_off) * APAD + kb + b_k]));
#pragma unroll
            for (int nf = 0; nf < 8; nf++)
                mma_tf32(o[nf], pa[0], pa[1], pa[2], pa[3], bf[nf][0], bf[nf][1]);
        }
        __syncwarp();
    }

    const float inv0 = 1.0f / l0;
    const float inv1 = 1.0f / l1;
    float* yr = y + ((size_t)b * Td + q0 + wm) * Cd + h * HDd;
#pragma unroll
    for (int nf = 0; nf < 8; nf++) {
        const int c = nf * 8 + tig * 2;
        float2 w0, w1;
        w0.x = to_tf32(o[nf][0] * inv0); w0.y = to_tf32(o[nf][1] * inv0);
        w1.x = to_tf32(o[nf][2] * inv1); w1.y = to_tf32(o[nf][3] * inv1);
        *(float2*)&yr[(size_t)grp * Cd + c]       = w0;
        *(float2*)&yr[(size_t)(grp + 8) * Cd + c] = w1;
    }
}

// ---------------------------------------------------------------------------
extern "C" void kernel_launch(void* const* d_in, const int* in_sizes, int n_in,
                              void* d_out, int out_size)
{
    const float* x  = (const float*)d_in[0];
    const float* Wa = (const float*)d_in[1];
    const float* ba = (const float*)d_in[2];
    const float* Wp = (const float*)d_in[3];
    const float* bp = (const float*)d_in[4];
    float* out = (float*)d_out;

    float *qkv_p, *y_p, *xr_p, *war_p, *wpr_p;
    cudaGetSymbolAddress((void**)&qkv_p, g_qkv);
    cudaGetSymbolAddress((void**)&y_p,   g_y);
    cudaGetSymbolAddress((void**)&xr_p,  g_xr);
    cudaGetSymbolAddress((void**)&war_p, g_war);
    cudaGetSymbolAddress((void**)&wpr_p, g_wpr);

    cudaFuncSetAttribute(gemm_tn<true>,  cudaFuncAttributeMaxDynamicSharedMemorySize, GEMM_SMEM_BYTES);
    cudaFuncSetAttribute(gemm_tn<false>, cudaFuncAttributeMaxDynamicSharedMemorySize, GEMM_SMEM_BYTES);
    cudaFuncSetAttribute(attn_tc,        cudaFuncAttributeMaxDynamicSharedMemorySize, ATTN_SMEM_BYTES);

    round4_kernel<<<(Md * Cd / 4 + 255) / 256, 256>>>((const float4*)x, (float4*)xr_p, Md * Cd / 4);
    transpose_round<<<dim3(C3 / 32, Cd / 32), dim3(32, 8)>>>(Wa, war_p, Cd, C3);
    transpose_round<<<dim3(Cd / 32, Cd / 32), dim3(32, 8)>>>(Wp, wpr_p, Cd, Cd);

    gemm_tn<true><<<dim3(C3 / 128, Md / 128), 256, GEMM_SMEM_BYTES>>>(
        xr_p, war_p, ba, qkv_p, Md, C3, Cd);

    attn_tc<<<dim3(Td / 128, Hd, Bd), 256, ATTN_SMEM_BYTES>>>(qkv_p, y_p);

    gemm_tn<false><<<dim3(Cd / 128, Md / 128), 256, GEMM_SMEM_BYTES>>>(
        y_p, wpr_p, bp, out, Md, Cd, Cd);
}

// round 7
// speedup vs baseline: 7.7819x; 1.8537x over previous
#include <cuda_runtime.h>
#include <cuda_fp16.h>
#include <math_constants.h>
#include <cstdint>

// Problem constants
#define Bd   8
#define Td   1024
#define Cd   768
#define Hd   12
#define HDd  64
#define C3   2304
#define Md   (Bd * Td)   // 8192

// Scratch (__device__ globals; allocation-free rule)
__device__ __half g_qkvh[(size_t)Md * C3];
__device__ __half g_yh  [(size_t)Md * Cd];
__device__ __half g_xh  [(size_t)Md * Cd];
__device__ __half g_wah [(size_t)C3 * Cd];   // W_attn^T [2304][768]
__device__ __half g_wph [(size_t)Cd * Cd];   // W_proj^T [768][768]

// ---------------------------------------------------------------------------
__device__ __forceinline__ uint32_t sptr(const void* p) {
    return (uint32_t)__cvta_generic_to_shared(p);
}

__device__ __forceinline__ void mma_f16(float c[4],
                                        uint32_t a0, uint32_t a1, uint32_t a2, uint32_t a3,
                                        uint32_t b0, uint32_t b1) {
    asm volatile(
        "mma.sync.aligned.m16n8k16.row.col.f32.f16.f16.f32 "
        "{%0,%1,%2,%3}, {%4,%5,%6,%7}, {%8,%9}, {%0,%1,%2,%3};"
        : "+f"(c[0]), "+f"(c[1]), "+f"(c[2]), "+f"(c[3])
        : "r"(a0), "r"(a1), "r"(a2), "r"(a3), "r"(b0), "r"(b1));
}

__device__ __forceinline__ void ldsm4(uint32_t& r0, uint32_t& r1,
                                      uint32_t& r2, uint32_t& r3, uint32_t addr) {
    asm volatile("ldmatrix.sync.aligned.m8n8.x4.shared.b16 {%0,%1,%2,%3}, [%4];"
                 : "=r"(r0), "=r"(r1), "=r"(r2), "=r"(r3) : "r"(addr));
}

__device__ __forceinline__ void ldsm4t(uint32_t& r0, uint32_t& r1,
                                       uint32_t& r2, uint32_t& r3, uint32_t addr) {
    asm volatile("ldmatrix.sync.aligned.m8n8.x4.trans.shared.b16 {%0,%1,%2,%3}, [%4];"
                 : "=r"(r0), "=r"(r1), "=r"(r2), "=r"(r3) : "r"(addr));
}

__device__ __forceinline__ void cp16(uint32_t dst, const void* src) {
    asm volatile("cp.async.cg.shared.global [%0], [%1], 16;\n" :: "r"(dst), "l"(src));
}
__device__ __forceinline__ void cp_commit() {
    asm volatile("cp.async.commit_group;\n");
}
template <int N>
__device__ __forceinline__ void cp_wait() {
    asm volatile("cp.async.wait_group %0;\n" :: "n"(N));
}

// ---------------------------------------------------------------------------
// Prep kernels: fp32 -> fp16
// ---------------------------------------------------------------------------
__global__ void f2h_kernel(const float4* __restrict__ in, __half2* __restrict__ out, int n4) {
    int i = blockIdx.x * blockDim.x + threadIdx.x;
    if (i < n4) {
        float4 v = in[i];
        out[i * 2 + 0] = __floats2half2_rn(v.x, v.y);
        out[i * 2 + 1] = __floats2half2_rn(v.z, v.w);
    }
}

// in float [R][C] -> out half [C][R]
__global__ void transpose_h(const float* __restrict__ in, __half* __restrict__ out,
                            int R, int C) {
    __shared__ float t[32][33];
    const int bx = blockIdx.x * 32;
    const int by = blockIdx.y * 32;
#pragma unroll
    for (int i = 0; i < 4; i++) {
        int y = by + threadIdx.y + i * 8;
        t[threadIdx.y + i * 8][threadIdx.x] = in[(size_t)y * C + bx + threadIdx.x];
    }
    __syncthreads();
#pragma unroll
    for (int i = 0; i < 4; i++) {
        int oy = bx + threadIdx.y + i * 8;
        out[(size_t)oy * R + by + threadIdx.x] = __float2half_rn(t[threadIdx.x][threadIdx.y + i * 8]);
    }
}

// ---------------------------------------------------------------------------
// FP16 TN GEMM + bias: C[M,N] = A[M,K] @ BT[N,K]^T + bias[N]
// 128x128 tile, K-chunk 32 halves, 4-stage cp.async, swizzled smem, 2 CTAs/SM.
// ---------------------------------------------------------------------------
#define GK     32                           // halves per k-chunk
#define STG    4
#define TILE_B (128 * GK * 2)               // 8 KB per operand per stage
#define GEMM_SMEM_BYTES (2 * STG * TILE_B)  // 64 KB

// byte offset of (row r, half-col colh) within one tile; conflict-free swizzle
__device__ __forceinline__ uint32_t hswz(int r, int colh) {
    return (uint32_t)(r * 64 + ((((colh) >> 3) ^ ((r >> 1) & 3)) << 4) + ((colh & 7) << 1));
}

template <bool HALF_OUT>
__global__ __launch_bounds__(256, 2) void gemm_h(
    const __half* __restrict__ A,    // [M][K]
    const __half* __restrict__ BT,   // [N][K]
    const float* __restrict__ bias,
    void* __restrict__ Cout,
    int M, int N, int K)
{
    extern __shared__ char smem[];
    const uint32_t As_s = sptr(smem);
    const uint32_t Bs_s = As_s + STG * TILE_B;

    const int tid  = threadIdx.x;
    const int wid  = tid >> 5;
    const int lane = tid & 31;
    const int grp  = lane >> 2;
    const int tig  = lane & 3;

    const int m0 = blockIdx.y * 128;
    const int n0 = blockIdx.x * 128;
    const int wm = (wid & 1) * 64;
    const int wn = (wid >> 1) * 32;

    // fragment lane addressing
    const int a_row = lane & 15;
    const int a_ch  = (lane >> 4);          // +0/+1 chunk within k16
    const int b_row = (lane & 7) + ((lane >> 4) & 1) * 8;
    const int b_ch  = (lane >> 3) & 1;

    float acc[4][4][4];
#pragma unroll
    for (int i = 0; i < 4; i++)
#pragma unroll
        for (int j = 0; j < 4; j++)
#pragma unroll
            for (int r = 0; r < 4; r++) acc[i][j][r] = 0.0f;

    const int nk = K / GK;   // 24

    // cp.async: 512 chunks per operand per stage, 2 per thread
    auto issue = [&](int t) {
        const int s = t % STG;
        const uint32_t ab = As_s + (uint32_t)s * TILE_B;
        const uint32_t bb = Bs_s + (uint32_t)s * TILE_B;
        const int k0 = t * GK;
#pragma unroll
        for (int i = 0; i < 2; i++) {
            const int g = tid + i * 256;     // 0..511
            const int r = g >> 2;            // row 0..127
            const int c = g & 3;             // chunk 0..3
            const uint32_t so = (uint32_t)(r * 64 + ((c ^ ((r >> 1) & 3)) << 4));
            cp16(ab + so, &A [(size_t)(m0 + r) * K + k0 + c * 8]);
            cp16(bb + so, &BT[(size_t)(n0 + r) * K + k0 + c * 8]);
        }
    };

#pragma unroll
    for (int t = 0; t < STG - 1; t++) {
        issue(t);
        cp_commit();
    }

    for (int t = 0; t < nk; t++) {
        const int pre = t + STG - 1;
        if (pre < nk) issue(pre);
        cp_commit();
        cp_wait<STG - 1>();
        __syncthreads();

        const int s = t % STG;
        const uint32_t ab = As_s + (uint32_t)s * TILE_B;
        const uint32_t bb = Bs_s + (uint32_t)s * TILE_B;

#pragma unroll
        for (int ks = 0; ks < 2; ks++) {     // two k16 slices per 32-half chunk
            const int kc = ks * 2;           // base chunk of this k16
            uint32_t a[4][4];
            uint32_t b[4][2];
#pragma unroll
            for (int mf = 0; mf < 4; mf++) {
                const int r = wm + mf * 16 + a_row;
                ldsm4(a[mf][0], a[mf][1], a[mf][2], a[mf][3],
                      ab + (uint32_t)(r * 64 + (((kc + a_ch) ^ ((r >> 1) & 3)) << 4)));
            }
#pragma unroll
            for (int p = 0; p < 2; p++) {
                const int r = wn + p * 16 + b_row;
                ldsm4(b[2 * p][0], b[2 * p][1], b[2 * p + 1][0], b[2 * p + 1][1],
                      bb + (uint32_t)(r * 64 + (((kc + b_ch) ^ ((r >> 1) & 3)) << 4)));
            }
#pragma unroll
            for (int mf = 0; mf < 4; mf++)
#pragma unroll
                for (int nf = 0; nf < 4; nf++)
                    mma_f16(acc[mf][nf],
                            a[mf][0], a[mf][1], a[mf][2], a[mf][3],
                            b[nf][0], b[nf][1]);
        }
        __syncthreads();
    }

    // epilogue
#pragma unroll
    for (int nf = 0; nf < 4; nf++) {
        const int col = n0 + wn + nf * 8 + tig * 2;
        const float bx = bias[col];
        const float by = bias[col + 1];
#pragma unroll
        for (int mf = 0; mf < 4; mf++) {
            const int row0 = m0 + wm + mf * 16 + grp;
            const int row1 = row0 + 8;
            const float o00 = acc[mf][nf][0] + bx;
            const float o01 = acc[mf][nf][1] + by;
            const float o10 = acc[mf][nf][2] + bx;
            const float o11 = acc[mf][nf][3] + by;
            if (HALF_OUT) {
                __half2* Ch = (__half2*)Cout;
                Ch[((size_t)row0 * N + col) >> 1] = __floats2half2_rn(o00, o01);
                Ch[((size_t)row1 * N + col) >> 1] = __floats2half2_rn(o10, o11);
            } else {
                float* Cf = (float*)Cout;
                *(float2*)&Cf[(size_t)row0 * N + col] = make_float2(o00, o01);
                *(float2*)&Cf[(size_t)row1 * N + col] = make_float2(o10, o11);
            }
        }
    }
}

// ---------------------------------------------------------------------------
// FP16 tensor-core flash attention. Block (qt,h,b), 8 warps, 128-row q tile.
// K,V row-major half in smem (pad 72 halves); V fragments via ldmatrix.trans.
// ---------------------------------------------------------------------------
#define PADH 72
#define ATTN_SMEM_BYTES ((64 * PADH + 64 * PADH + 8 * 16 * PADH) * 2)

__global__ __launch_bounds__(256, 2) void attn_h(
    const __half* __restrict__ qkv, __half* __restrict__ y)
{
    extern __shared__ char smc[];
    __half* Ks = (__half*)smc;                 // [64][PADH]  K[j][d]
    __half* Vs = Ks + 64 * PADH;               // [64][PADH]  V[j][d]
    __half* Ps = Vs + 64 * PADH;               // [8][16][PADH] per-warp Q/P

    const int tid  = threadIdx.x;
    const int wid  = tid >> 5;
    const int lane = tid & 31;
    const int grp  = lane >> 2;
    const int tig  = lane & 3;

    const int qt = blockIdx.x;
    const int h  = blockIdx.y;
    const int b  = blockIdx.z;
    const int q0 = qt * 128;
    const int wm = wid * 16;

    const __half* base = qkv + (size_t)b * Td * C3 + h * 192;
    __half* Pw = Ps + wid * 16 * PADH;
    const uint32_t Pw_s = sptr(Pw);
    const uint32_t Ks_s = sptr(Ks);
    const uint32_t Vs_s = sptr(Vs);

    const int a_row = lane & 15;
    const int a_c8  = (lane >> 4) * 8;          // half offset within k16
    const int b_row = (lane & 7) + ((lane >> 4) & 1) * 8;
    const int b_c8  = ((lane >> 3) & 1) * 8;
    const int v_row = lane & 15;                // trans addressing
    const int v_c8  = (lane >> 4) * 8;

    // stage Q (x 0.125) into Pw
    const __half2 h125 = __float2half2_rn(0.125f);
#pragma unroll
    for (int i = 0; i < 4; i++) {
        const int f = i * 32 + lane;            // 0..127
        const int r = f >> 3, c8 = (f & 7) * 8;
        uint4 v = *(const uint4*)(base + (size_t)(q0 + wm + r) * C3 + c8);
        __half2* hv = (__half2*)&v;
#pragma unroll
        for (int u = 0; u < 4; u++) hv[u] = __hmul2(hv[u], h125);
        *(uint4*)&Pw[r * PADH + c8] = v;
    }
    __syncwarp();

    uint32_t Qa[4][4];
#pragma unroll
    for (int k = 0; k < 4; k++)
        ldsm4(Qa[k][0], Qa[k][1], Qa[k][2], Qa[k][3],
              Pw_s + (uint32_t)(a_row * PADH + k * 16 + a_c8) * 2u);

    float o[8][4];
#pragma unroll
    for (int nf = 0; nf < 8; nf++)
#pragma unroll
        for (int r = 0; r < 4; r++) o[nf][r] = 0.0f;

    float mx0 = -CUDART_INF_F, mx1 = -CUDART_INF_F;
    float l0 = 0.0f, l1 = 0.0f;

    const int row0 = q0 + wm + grp;
    const int row1 = row0 + 8;
    const int nkt  = 2 * (qt + 1);

    for (int kt = 0; kt < nkt; kt++) {
        const int k0 = kt * 64;
        __syncthreads();

        // K,V tiles via cp.async: 512 chunks each, 2 per thread
#pragma unroll
        for (int i = 0; i < 2; i++) {
            const int g = tid + i * 256;        // 0..511
            const int j = g >> 3, c8 = (g & 7) * 8;
            const uint32_t dst = (uint32_t)(j * PADH + c8) * 2u;
            cp16(Ks_s + dst, base + (size_t)(k0 + j) * C3 + 64 + c8);
            cp16(Vs_s + dst, base + (size_t)(k0 + j) * C3 + 128 + c8);
        }
        cp_commit();
        cp_wait<0>();
        __syncthreads();

        // S = Q @ K^T
        float sc[8][4];
#pragma unroll
        for (int nf = 0; nf < 8; nf++)
#pragma unroll
            for (int r = 0; r < 4; r++) sc[nf][r] = 0.0f;

#pragma unroll
        for (int k = 0; k < 4; k++) {           // k16 slice over d
            uint32_t bf[8][2];
#pragma unroll
            for (int p = 0; p < 4; p++)
                ldsm4(bf[2 * p][0], bf[2 * p][1], bf[2 * p + 1][0], bf[2 * p + 1][1],
                      Ks_s + (uint32_t)((p * 16 + b_row) * PADH + k * 16 + b_c8) * 2u);
#pragma unroll
            for (int nf = 0; nf < 8; nf++)
                mma_f16(sc[nf], Qa[k][0], Qa[k][1], Qa[k][2], Qa[k][3],
                        bf[nf][0], bf[nf][1]);
        }

        // causal mask
        if (k0 + 64 > q0) {
#pragma unroll
            for (int nf = 0; nf < 8; nf++) {
                const int c = k0 + nf * 8 + tig * 2;
                if (c     > row0) sc[nf][0] = -CUDART_INF_F;
                if (c + 1 > row0) sc[nf][1] = -CUDART_INF_F;
                if (c     > row1) sc[nf][2] = -CUDART_INF_F;
                if (c + 1 > row1) sc[nf][3] = -CUDART_INF_F;
            }
        }

        // online softmax
        float mt0 = -CUDART_INF_F, mt1 = -CUDART_INF_F;
#pragma unroll
        for (int nf = 0; nf < 8; nf++) {
            mt0 = fmaxf(mt0, fmaxf(sc[nf][0], sc[nf][1]));
            mt1 = fmaxf(mt1, fmaxf(sc[nf][2], sc[nf][3]));
        }
        mt0 = fmaxf(mt0, __shfl_xor_sync(0xffffffffu, mt0, 1));
        mt0 = fmaxf(mt0, __shfl_xor_sync(0xffffffffu, mt0, 2));
        mt1 = fmaxf(mt1, __shfl_xor_sync(0xffffffffu, mt1, 1));
        mt1 = fmaxf(mt1, __shfl_xor_sync(0xffffffffu, mt1, 2));

        const float mn0 = fmaxf(mx0, mt0);
        const float mn1 = fmaxf(mx1, mt1);
        const float corr0 = __expf(mx0 - mn0);
        const float corr1 = __expf(mx1 - mn1);

        float ls0 = 0.0f, ls1 = 0.0f;
#pragma unroll
        for (int nf = 0; nf < 8; nf++) {
            const float p0 = __expf(sc[nf][0] - mn0);
            const float p1 = __expf(sc[nf][1] - mn0);
            const float p2 = __expf(sc[nf][2] - mn1);
            const float p3 = __expf(sc[nf][3] - mn1);
            ls0 += p0 + p1;
            ls1 += p2 + p3;
            const int c = nf * 8 + tig * 2;
            *(__half2*)&Pw[grp * PADH + c]       = __floats2half2_rn(p0, p1);
            *(__half2*)&Pw[(grp + 8) * PADH + c] = __floats2half2_rn(p2, p3);
        }
        ls0 += __shfl_xor_sync(0xffffffffu, ls0, 1);
        ls0 += __shfl_xor_sync(0xffffffffu, ls0, 2);
        ls1 += __shfl_xor_sync(0xffffffffu, ls1, 1);
        ls1 += __shfl_xor_sync(0xffffffffu, ls1, 2);

        l0 = l0 * corr0 + ls0;
        l1 = l1 * corr1 + ls1;
        mx0 = mn0; mx1 = mn1;

#pragma unroll
        for (int nf = 0; nf < 8; nf++) {
            o[nf][0] *= corr0; o[nf][1] *= corr0;
            o[nf][2] *= corr1; o[nf][3] *= corr1;
        }

        __syncwarp();

        // O += P @ V   (V fragments via ldmatrix.trans on row-major V)
#pragma unroll
        for (int k = 0; k < 4; k++) {           // k16 slice over j
            uint32_t pa[4];
            ldsm4(pa[0], pa[1], pa[2], pa[3],
                  Pw_s + (uint32_t)(a_row * PADH + k * 16 + a_c8) * 2u);
            uint32_t bf[8][2];
#pragma unroll
            for (int p = 0; p < 4; p++)
                ldsm4t(bf[2 * p][0], bf[2 * p][1], bf[2 * p + 1][0], bf[2 * p + 1][1],
                       Vs_s + (uint32_t)((k * 16 + v_row) * PADH + p * 16 + v_c8) * 2u);
#pragma unroll
            for (int nf = 0; nf < 8; nf++)
                mma_f16(o[nf], pa[0], pa[1], pa[2], pa[3], bf[nf][0], bf[nf][1]);
        }
        __syncwarp();
    }

    const float inv0 = 1.0f / l0;
    const float inv1 = 1.0f / l1;
    __half* yr = y + ((size_t)b * Td + q0 + wm) * Cd + h * HDd;
#pragma unroll
    for (int nf = 0; nf < 8; nf++) {
        const int c = nf * 8 + tig * 2;
        *(__half2*)&yr[(size_t)grp * Cd + c] =
            __floats2half2_rn(o[nf][0] * inv0, o[nf][1] * inv0);
        *(__half2*)&yr[(size_t)(grp + 8) * Cd + c] =
            __floats2half2_rn(o[nf][2] * inv1, o[nf][3] * inv1);
    }
}

// ---------------------------------------------------------------------------
extern "C" void kernel_launch(void* const* d_in, const int* in_sizes, int n_in,
                              void* d_out, int out_size)
{
    const float* x  = (const float*)d_in[0];
    const float* Wa = (const float*)d_in[1];
    const float* ba = (const float*)d_in[2];
    const float* Wp = (const float*)d_in[3];
    const float* bp = (const float*)d_in[4];
    float* out = (float*)d_out;

    __half *qkvh, *yh, *xh, *wah, *wph;
    cudaGetSymbolAddress((void**)&qkvh, g_qkvh);
    cudaGetSymbolAddress((void**)&yh,   g_yh);
    cudaGetSymbolAddress((void**)&xh,   g_xh);
    cudaGetSymbolAddress((void**)&wah,  g_wah);
    cudaGetSymbolAddress((void**)&wph,  g_wph);

    cudaFuncSetAttribute(gemm_h<true>,  cudaFuncAttributeMaxDynamicSharedMemorySize, GEMM_SMEM_BYTES);
    cudaFuncSetAttribute(gemm_h<false>, cudaFuncAttributeMaxDynamicSharedMemorySize, GEMM_SMEM_BYTES);
    cudaFuncSetAttribute(attn_h,        cudaFuncAttributeMaxDynamicSharedMemorySize, ATTN_SMEM_BYTES);

    // prep
    f2h_kernel<<<(Md * Cd / 4 + 255) / 256, 256>>>((const float4*)x, (__half2*)xh, Md * Cd / 4);
    transpose_h<<<dim3(C3 / 32, Cd / 32), dim3(32, 8)>>>(Wa, wah, Cd, C3);
    transpose_h<<<dim3(Cd / 32, Cd / 32), dim3(32, 8)>>>(Wp, wph, Cd, Cd);

    // 1) qkv = x @ W_attn + b_attn  (half out)
    gemm_h<true><<<dim3(C3 / 128, Md / 128), 256, GEMM_SMEM_BYTES>>>(
        xh, wah, ba, qkvh, Md, C3, Cd);

    // 2) attention (half in/out)
    attn_h<<<dim3(Td / 128, Hd, Bd), 256, ATTN_SMEM_BYTES>>>(qkvh, yh);

    // 3) out = y @ W_proj + b_proj  (fp32 out)
    gemm_h<false><<<dim3(Cd / 128, Md / 128), 256, GEMM_SMEM_BYTES>>>(
        yh, wph, bp, out, Md, Cd, Cd);
}

// round 8
// speedup vs baseline: 8.0704x; 1.0371x over previous
#include <cuda_runtime.h>
#include <cuda_fp16.h>
#include <math_constants.h>
#include <cstdint>

// Problem constants
#define Bd   8
#define Td   1024
#define Cd   768
#define Hd   12
#define HDd  64
#define C3   2304
#define Md   (Bd * Td)   // 8192

// Scratch (__device__ globals; allocation-free rule)
__device__ __half g_qkvh[(size_t)Md * C3];
__device__ __half g_yh  [(size_t)Md * Cd];
__device__ __half g_xh  [(size_t)Md * Cd];
__device__ __half g_wah [(size_t)C3 * Cd];   // W_attn^T [2304][768]
__device__ __half g_wph [(size_t)Cd * Cd];   // W_proj^T [768][768]

// ---------------------------------------------------------------------------
__device__ __forceinline__ uint32_t sptr(const void* p) {
    return (uint32_t)__cvta_generic_to_shared(p);
}

__device__ __forceinline__ float fexp2(float x) {
    float r;
    asm("ex2.approx.f32 %0, %1;" : "=f"(r) : "f"(x));
    return r;
}

__device__ __forceinline__ void mma_f16(float c[4],
                                        uint32_t a0, uint32_t a1, uint32_t a2, uint32_t a3,
                                        uint32_t b0, uint32_t b1) {
    asm volatile(
        "mma.sync.aligned.m16n8k16.row.col.f32.f16.f16.f32 "
        "{%0,%1,%2,%3}, {%4,%5,%6,%7}, {%8,%9}, {%0,%1,%2,%3};"
        : "+f"(c[0]), "+f"(c[1]), "+f"(c[2]), "+f"(c[3])
        : "r"(a0), "r"(a1), "r"(a2), "r"(a3), "r"(b0), "r"(b1));
}

__device__ __forceinline__ void ldsm4(uint32_t& r0, uint32_t& r1,
                                      uint32_t& r2, uint32_t& r3, uint32_t addr) {
    asm volatile("ldmatrix.sync.aligned.m8n8.x4.shared.b16 {%0,%1,%2,%3}, [%4];"
                 : "=r"(r0), "=r"(r1), "=r"(r2), "=r"(r3) : "r"(addr));
}

__device__ __forceinline__ void ldsm4t(uint32_t& r0, uint32_t& r1,
                                       uint32_t& r2, uint32_t& r3, uint32_t addr) {
    asm volatile("ldmatrix.sync.aligned.m8n8.x4.trans.shared.b16 {%0,%1,%2,%3}, [%4];"
                 : "=r"(r0), "=r"(r1), "=r"(r2), "=r"(r3) : "r"(addr));
}

__device__ __forceinline__ void cp16(uint32_t dst, const void* src) {
    asm volatile("cp.async.cg.shared.global [%0], [%1], 16;\n" :: "r"(dst), "l"(src));
}
__device__ __forceinline__ void cp_commit() {
    asm volatile("cp.async.commit_group;\n");
}
template <int N>
__device__ __forceinline__ void cp_wait() {
    asm volatile("cp.async.wait_group %0;\n" :: "n"(N));
}

// ---------------------------------------------------------------------------
// Prep kernels: fp32 -> fp16
// ---------------------------------------------------------------------------
__global__ void f2h_kernel(const float4* __restrict__ in, __half2* __restrict__ out, int n4) {
    int i = blockIdx.x * blockDim.x + threadIdx.x;
    if (i < n4) {
        float4 v = in[i];
        out[i * 2 + 0] = __floats2half2_rn(v.x, v.y);
        out[i * 2 + 1] = __floats2half2_rn(v.z, v.w);
    }
}

__global__ void transpose_h(const float* __restrict__ in, __half* __restrict__ out,
                            int R, int C) {
    __shared__ float t[32][33];
    const int bx = blockIdx.x * 32;
    const int by = blockIdx.y * 32;
#pragma unroll
    for (int i = 0; i < 4; i++) {
        int y = by + threadIdx.y + i * 8;
        t[threadIdx.y + i * 8][threadIdx.x] = in[(size_t)y * C + bx + threadIdx.x];
    }
    __syncthreads();
#pragma unroll
    for (int i = 0; i < 4; i++) {
        int oy = bx + threadIdx.y + i * 8;
        out[(size_t)oy * R + by + threadIdx.x] = __float2half_rn(t[threadIdx.x][threadIdx.y + i * 8]);
    }
}

// ---------------------------------------------------------------------------
// FP16 TN GEMM + bias (unchanged from R7 — known good)
// ---------------------------------------------------------------------------
#define GK     32
#define STG    4
#define TILE_B (128 * GK * 2)
#define GEMM_SMEM_BYTES (2 * STG * TILE_B)

template <bool HALF_OUT>
__global__ __launch_bounds__(256, 2) void gemm_h(
    const __half* __restrict__ A,
    const __half* __restrict__ BT,
    const float* __restrict__ bias,
    void* __restrict__ Cout,
    int M, int N, int K)
{
    extern __shared__ char smem[];
    const uint32_t As_s = sptr(smem);
    const uint32_t Bs_s = As_s + STG * TILE_B;

    const int tid  = threadIdx.x;
    const int wid  = tid >> 5;
    const int lane = tid & 31;
    const int grp  = lane >> 2;
    const int tig  = lane & 3;

    const int m0 = blockIdx.y * 128;
    const int n0 = blockIdx.x * 128;
    const int wm = (wid & 1) * 64;
    const int wn = (wid >> 1) * 32;

    const int a_row = lane & 15;
    const int a_ch  = (lane >> 4);
    const int b_row = (lane & 7) + ((lane >> 4) & 1) * 8;
    const int b_ch  = (lane >> 3) & 1;

    float acc[4][4][4];
#pragma unroll
    for (int i = 0; i < 4; i++)
#pragma unroll
        for (int j = 0; j < 4; j++)
#pragma unroll
            for (int r = 0; r < 4; r++) acc[i][j][r] = 0.0f;

    const int nk = K / GK;

    auto issue = [&](int t) {
        const int s = t % STG;
        const uint32_t ab = As_s + (uint32_t)s * TILE_B;
        const uint32_t bb = Bs_s + (uint32_t)s * TILE_B;
        const int k0 = t * GK;
#pragma unroll
        for (int i = 0; i < 2; i++) {
            const int g = tid + i * 256;
            const int r = g >> 2;
            const int c = g & 3;
            const uint32_t so = (uint32_t)(r * 64 + ((c ^ ((r >> 1) & 3)) << 4));
            cp16(ab + so, &A [(size_t)(m0 + r) * K + k0 + c * 8]);
            cp16(bb + so, &BT[(size_t)(n0 + r) * K + k0 + c * 8]);
        }
    };

#pragma unroll
    for (int t = 0; t < STG - 1; t++) {
        issue(t);
        cp_commit();
    }

    for (int t = 0; t < nk; t++) {
        const int pre = t + STG - 1;
        if (pre < nk) issue(pre);
        cp_commit();
        cp_wait<STG - 1>();
        __syncthreads();

        const int s = t % STG;
        const uint32_t ab = As_s + (uint32_t)s * TILE_B;
        const uint32_t bb = Bs_s + (uint32_t)s * TILE_B;

#pragma unroll
        for (int ks = 0; ks < 2; ks++) {
            const int kc = ks * 2;
            uint32_t a[4][4];
            uint32_t b[4][2];
#pragma unroll
            for (int mf = 0; mf < 4; mf++) {
                const int r = wm + mf * 16 + a_row;
                ldsm4(a[mf][0], a[mf][1], a[mf][2], a[mf][3],
                      ab + (uint32_t)(r * 64 + (((kc + a_ch) ^ ((r >> 1) & 3)) << 4)));
            }
#pragma unroll
            for (int p = 0; p < 2; p++) {
                const int r = wn + p * 16 + b_row;
                ldsm4(b[2 * p][0], b[2 * p][1], b[2 * p + 1][0], b[2 * p + 1][1],
                      bb + (uint32_t)(r * 64 + (((kc + b_ch) ^ ((r >> 1) & 3)) << 4)));
            }
#pragma unroll
            for (int mf = 0; mf < 4; mf++)
#pragma unroll
                for (int nf = 0; nf < 4; nf++)
                    mma_f16(acc[mf][nf],
                            a[mf][0], a[mf][1], a[mf][2], a[mf][3],
                            b[nf][0], b[nf][1]);
        }
        __syncthreads();
    }

#pragma unroll
    for (int nf = 0; nf < 4; nf++) {
        const int col = n0 + wn + nf * 8 + tig * 2;
        const float bx = bias[col];
        const float by = bias[col + 1];
#pragma unroll
        for (int mf = 0; mf < 4; mf++) {
            const int row0 = m0 + wm + mf * 16 + grp;
            const int row1 = row0 + 8;
            const float o00 = acc[mf][nf][0] + bx;
            const float o01 = acc[mf][nf][1] + by;
            const float o10 = acc[mf][nf][2] + bx;
            const float o11 = acc[mf][nf][3] + by;
            if (HALF_OUT) {
                __half2* Ch = (__half2*)Cout;
                Ch[((size_t)row0 * N + col) >> 1] = __floats2half2_rn(o00, o01);
                Ch[((size_t)row1 * N + col) >> 1] = __floats2half2_rn(o10, o11);
            } else {
                float* Cf = (float*)Cout;
                *(float2*)&Cf[(size_t)row0 * N + col] = make_float2(o00, o01);
                *(float2*)&Cf[(size_t)row1 * N + col] = make_float2(o10, o11);
            }
        }
    }
}

// ---------------------------------------------------------------------------
// FP16 flash attention: double-buffered K/V cp.async, exp2 softmax,
// heavy-first q-tile order. Block (qt,h,b), 8 warps, 128-row q tile.
// ---------------------------------------------------------------------------
#define PADH 72
#define KV_STAGE_H (2 * 64 * PADH)                 // halves per stage (K+V)
#define ATTN_SMEM_BYTES ((2 * KV_STAGE_H + 8 * 16 * PADH) * 2)

__global__ __launch_bounds__(256, 2) void attn_h(
    const __half* __restrict__ qkv, __half* __restrict__ y)
{
    extern __shared__ char smc[];
    __half* KV = (__half*)smc;                     // [2][ K(64xPADH) | V(64xPADH) ]
    __half* Ps = KV + 2 * KV_STAGE_H;              // [8][16][PADH]

    const int tid  = threadIdx.x;
    const int wid  = tid >> 5;
    const int lane = tid & 31;
    const int grp  = lane >> 2;
    const int tig  = lane & 3;

    const int qt = (gridDim.x - 1) - blockIdx.x;   // heavy tiles first
    const int h  = blockIdx.y;
    const int b  = blockIdx.z;
    const int q0 = qt * 128;
    const int wm = wid * 16;

    const __half* base = qkv + (size_t)b * Td * C3 + h * 192;
    __half* Pw = Ps + wid * 16 * PADH;
    const uint32_t Pw_s = sptr(Pw);
    const uint32_t KV_s = sptr(KV);

    const int a_row = lane & 15;
    const int a_c8  = (lane >> 4) * 8;
    const int b_row = (lane & 7) + ((lane >> 4) & 1) * 8;
    const int b_c8  = ((lane >> 3) & 1) * 8;
    const int v_row = lane & 15;
    const int v_c8  = (lane >> 4) * 8;

    // stage Q scaled by 0.125*log2(e) (exp2 domain)
    const __half2 hs = __float2half2_rn(0.125f * 1.44269504f);
#pragma unroll
    for (int i = 0; i < 4; i++) {
        const int f = i * 32 + lane;
        const int r = f >> 3, c8 = (f & 7) * 8;
        uint4 v = *(const uint4*)(base + (size_t)(q0 + wm + r) * C3 + c8);
        __half2* hv = (__half2*)&v;
#pragma unroll
        for (int u = 0; u < 4; u++) hv[u] = __hmul2(hv[u], hs);
        *(uint4*)&Pw[r * PADH + c8] = v;
    }
    __syncwarp();

    uint32_t Qa[4][4];
#pragma unroll
    for (int k = 0; k < 4; k++)
        ldsm4(Qa[k][0], Qa[k][1], Qa[k][2], Qa[k][3],
              Pw_s + (uint32_t)(a_row * PADH + k * 16 + a_c8) * 2u);

    float o[8][4];
#pragma unroll
    for (int nf = 0; nf < 8; nf++)
#pragma unroll
        for (int r = 0; r < 4; r++) o[nf][r] = 0.0f;

    float mx0 = -CUDART_INF_F, mx1 = -CUDART_INF_F;
    float l0 = 0.0f, l1 = 0.0f;

    const int row0 = q0 + wm + grp;
    const int row1 = row0 + 8;
    const int nkt  = 2 * (qt + 1);

    // issue K/V tile kt into stage kt&1 (512 chunks, 2 per thread)
    auto issue_kv = [&](int kt) {
        const uint32_t sb = KV_s + (uint32_t)((kt & 1) * KV_STAGE_H) * 2u;
        const int k0 = kt * 64;
#pragma unroll
        for (int i = 0; i < 2; i++) {
            const int g = tid + i * 256;
            const int j = g >> 3, c8 = (g & 7) * 8;
            const uint32_t dst = (uint32_t)(j * PADH + c8) * 2u;
            cp16(sb + dst,                          base + (size_t)(k0 + j) * C3 + 64 + c8);
            cp16(sb + (uint32_t)(64 * PADH) * 2u + dst, base + (size_t)(k0 + j) * C3 + 128 + c8);
        }
    };

    issue_kv(0);
    cp_commit();

    for (int kt = 0; kt < nkt; kt++) {
        if (kt + 1 < nkt) {
            issue_kv(kt + 1);
            cp_commit();
            cp_wait<1>();          // current stage complete; next in flight
        } else {
            cp_wait<0>();
        }
        __syncthreads();

        const uint32_t Ks_s = KV_s + (uint32_t)((kt & 1) * KV_STAGE_H) * 2u;
        const uint32_t Vs_s = Ks_s + (uint32_t)(64 * PADH) * 2u;
        const int k0 = kt * 64;

        // S = Q @ K^T  (scores in exp2 domain)
        float sc[8][4];
#pragma unroll
        for (int nf = 0; nf < 8; nf++)
#pragma unroll
            for (int r = 0; r < 4; r++) sc[nf][r] = 0.0f;

#pragma unroll
        for (int k = 0; k < 4; k++) {
            uint32_t bf[8][2];
#pragma unroll
            for (int p = 0; p < 4; p++)
                ldsm4(bf[2 * p][0], bf[2 * p][1], bf[2 * p + 1][0], bf[2 * p + 1][1],
                      Ks_s + (uint32_t)((p * 16 + b_row) * PADH + k * 16 + b_c8) * 2u);
#pragma unroll
            for (int nf = 0; nf < 8; nf++)
                mma_f16(sc[nf], Qa[k][0], Qa[k][1], Qa[k][2], Qa[k][3],
                        bf[nf][0], bf[nf][1]);
        }

        // causal mask
        if (k0 + 64 > q0) {
#pragma unroll
            for (int nf = 0; nf < 8; nf++) {
                const int c = k0 + nf * 8 + tig * 2;
                if (c     > row0) sc[nf][0] = -CUDART_INF_F;
                if (c + 1 > row0) sc[nf][1] = -CUDART_INF_F;
                if (c     > row1) sc[nf][2] = -CUDART_INF_F;
                if (c + 1 > row1) sc[nf][3] = -CUDART_INF_F;
            }
        }

        // online softmax (base-2)
        float mt0 = -CUDART_INF_F, mt1 = -CUDART_INF_F;
#pragma unroll
        for (int nf = 0; nf < 8; nf++) {
            mt0 = fmaxf(mt0, fmaxf(sc[nf][0], sc[nf][1]));
            mt1 = fmaxf(mt1, fmaxf(sc[nf][2], sc[nf][3]));
        }
        mt0 = fmaxf(mt0, __shfl_xor_sync(0xffffffffu, mt0, 1));
        mt0 = fmaxf(mt0, __shfl_xor_sync(0xffffffffu, mt0, 2));
        mt1 = fmaxf(mt1, __shfl_xor_sync(0xffffffffu, mt1, 1));
        mt1 = fmaxf(mt1, __shfl_xor_sync(0xffffffffu, mt1, 2));

        const float mn0 = fmaxf(mx0, mt0);
        const float mn1 = fmaxf(mx1, mt1);
        const float corr0 = fexp2(mx0 - mn0);
        const float corr1 = fexp2(mx1 - mn1);

        float ls0 = 0.0f, ls1 = 0.0f;
#pragma unroll
        for (int nf = 0; nf < 8; nf++) {
            const float p0 = fexp2(sc[nf][0] - mn0);
            const float p1 = fexp2(sc[nf][1] - mn0);
            const float p2 = fexp2(sc[nf][2] - mn1);
            const float p3 = fexp2(sc[nf][3] - mn1);
            ls0 += p0 + p1;
            ls1 += p2 + p3;
            const int c = nf * 8 + tig * 2;
            *(__half2*)&Pw[grp * PADH + c]       = __floats2half2_rn(p0, p1);
            *(__half2*)&Pw[(grp + 8) * PADH + c] = __floats2half2_rn(p2, p3);
        }
        ls0 += __shfl_xor_sync(0xffffffffu, ls0, 1);
        ls0 += __shfl_xor_sync(0xffffffffu, ls0, 2);
        ls1 += __shfl_xor_sync(0xffffffffu, ls1, 1);
        ls1 += __shfl_xor_sync(0xffffffffu, ls1, 2);

        l0 = l0 * corr0 + ls0;
        l1 = l1 * corr1 + ls1;
        mx0 = mn0; mx1 = mn1;

#pragma unroll
        for (int nf = 0; nf < 8; nf++) {
            o[nf][0] *= corr0; o[nf][1] *= corr0;
            o[nf][2] *= corr1; o[nf][3] *= corr1;
        }

        __syncwarp();

        // O += P @ V
#pragma unroll
        for (int k = 0; k < 4; k++) {
            uint32_t pa[4];
            ldsm4(pa[0], pa[1], pa[2], pa[3],
                  Pw_s + (uint32_t)(a_row * PADH + k * 16 + a_c8) * 2u);
            uint32_t bf[8][2];
#pragma unroll
            for (int p = 0; p < 4; p++)
                ldsm4t(bf[2 * p][0], bf[2 * p][1], bf[2 * p + 1][0], bf[2 * p + 1][1],
                       Vs_s + (uint32_t)((k * 16 + v_row) * PADH + p * 16 + v_c8) * 2u);
#pragma unroll
            for (int nf = 0; nf < 8; nf++)
                mma_f16(o[nf], pa[0], pa[1], pa[2], pa[3], bf[nf][0], bf[nf][1]);
        }
        __syncthreads();   // all warps done with stage kt&1 before it's re-issued
    }

    const float inv0 = 1.0f / l0;
    const float inv1 = 1.0f / l1;
    __half* yr = y + ((size_t)b * Td + q0 + wm) * Cd + h * HDd;
#pragma unroll
    for (int nf = 0; nf < 8; nf++) {
        const int c = nf * 8 + tig * 2;
        *(__half2*)&yr[(size_t)grp * Cd + c] =
            __floats2half2_rn(o[nf][0] * inv0, o[nf][1] * inv0);
        *(__half2*)&yr[(size_t)(grp + 8) * Cd + c] =
            __floats2half2_rn(o[nf][2] * inv1, o[nf][3] * inv1);
    }
}

// ---------------------------------------------------------------------------
extern "C" void kernel_launch(void* const* d_in, const int* in_sizes, int n_in,
                              void* d_out, int out_size)
{
    const float* x  = (const float*)d_in[0];
    const float* Wa = (const float*)d_in[1];
    const float* ba = (const float*)d_in[2];
    const float* Wp = (const float*)d_in[3];
    const float* bp = (const float*)d_in[4];
    float* out = (float*)d_out;

    __half *qkvh, *yh, *xh, *wah, *wph;
    cudaGetSymbolAddress((void**)&qkvh, g_qkvh);
    cudaGetSymbolAddress((void**)&yh,   g_yh);
    cudaGetSymbolAddress((void**)&xh,   g_xh);
    cudaGetSymbolAddress((void**)&wah,  g_wah);
    cudaGetSymbolAddress((void**)&wph,  g_wph);

    cudaFuncSetAttribute(gemm_h<true>,  cudaFuncAttributeMaxDynamicSharedMemorySize, GEMM_SMEM_BYTES);
    cudaFuncSetAttribute(gemm_h<false>, cudaFuncAttributeMaxDynamicSharedMemorySize, GEMM_SMEM_BYTES);
    cudaFuncSetAttribute(attn_h,        cudaFuncAttributeMaxDynamicSharedMemorySize, ATTN_SMEM_BYTES);

    f2h_kernel<<<(Md * Cd / 4 + 255) / 256, 256>>>((const float4*)x, (__half2*)xh, Md * Cd / 4);
    transpose_h<<<dim3(C3 / 32, Cd / 32), dim3(32, 8)>>>(Wa, wah, Cd, C3);
    transpose_h<<<dim3(Cd / 32, Cd / 32), dim3(32, 8)>>>(Wp, wph, Cd, Cd);

    gemm_h<true><<<dim3(C3 / 128, Md / 128), 256, GEMM_SMEM_BYTES>>>(
        xh, wah, ba, qkvh, Md, C3, Cd);

    attn_h<<<dim3(Td / 128, Hd, Bd), 256, ATTN_SMEM_BYTES>>>(qkvh, yh);

    gemm_h<false><<<dim3(Cd / 128, Md / 128), 256, GEMM_SMEM_BYTES>>>(
        yh, wph, bp, out, Md, Cd, Cd);
}

// round 10
// speedup vs baseline: 8.2741x; 1.0252x over previous
#include <cuda_runtime.h>
#include <cuda_fp16.h>
#include <math_constants.h>
#include <cstdint>

// Problem constants
#define Bd   8
#define Td   1024
#define Cd   768
#define Hd   12
#define HDd  64
#define C3   2304
#define Md   (Bd * Td)   // 8192

// Scratch (__device__ globals; allocation-free rule)
__device__ __half g_qkvh[(size_t)Md * C3];
__device__ __half g_yh  [(size_t)Md * Cd];
__device__ __half g_xh  [(size_t)Md * Cd];
__device__ __half g_wah [(size_t)C3 * Cd];   // W_attn^T [2304][768]
__device__ __half g_wph [(size_t)Cd * Cd];   // W_proj^T [768][768]

// ---------------------------------------------------------------------------
__device__ __forceinline__ uint32_t sptr(const void* p) {
    return (uint32_t)__cvta_generic_to_shared(p);
}

__device__ __forceinline__ float fexp2(float x) {
    float r;
    asm("ex2.approx.f32 %0, %1;" : "=f"(r) : "f"(x));
    return r;
}

// pack two floats into one f16x2 register (RN), lo=a, hi=b
__device__ __forceinline__ uint32_t packh2(float a, float b) {
    uint32_t r;
    asm("cvt.rn.f16x2.f32 %0, %1, %2;" : "=r"(r) : "f"(b), "f"(a));
    return r;
}

__device__ __forceinline__ void mma_f16(float c[4],
                                        uint32_t a0, uint32_t a1, uint32_t a2, uint32_t a3,
                                        uint32_t b0, uint32_t b1) {
    asm volatile(
        "mma.sync.aligned.m16n8k16.row.col.f32.f16.f16.f32 "
        "{%0,%1,%2,%3}, {%4,%5,%6,%7}, {%8,%9}, {%0,%1,%2,%3};"
        : "+f"(c[0]), "+f"(c[1]), "+f"(c[2]), "+f"(c[3])
        : "r"(a0), "r"(a1), "r"(a2), "r"(a3), "r"(b0), "r"(b1));
}

__device__ __forceinline__ void ldsm4(uint32_t& r0, uint32_t& r1,
                                      uint32_t& r2, uint32_t& r3, uint32_t addr) {
    asm volatile("ldmatrix.sync.aligned.m8n8.x4.shared.b16 {%0,%1,%2,%3}, [%4];"
                 : "=r"(r0), "=r"(r1), "=r"(r2), "=r"(r3) : "r"(addr));
}

__device__ __forceinline__ void ldsm4t(uint32_t& r0, uint32_t& r1,
                                       uint32_t& r2, uint32_t& r3, uint32_t addr) {
    asm volatile("ldmatrix.sync.aligned.m8n8.x4.trans.shared.b16 {%0,%1,%2,%3}, [%4];"
                 : "=r"(r0), "=r"(r1), "=r"(r2), "=r"(r3) : "r"(addr));
}

__device__ __forceinline__ void cp16(uint32_t dst, const void* src) {
    asm volatile("cp.async.cg.shared.global [%0], [%1], 16;\n" :: "r"(dst), "l"(src));
}
__device__ __forceinline__ void cp_commit() {
    asm volatile("cp.async.commit_group;\n");
}
template <int N>
__device__ __forceinline__ void cp_wait() {
    asm volatile("cp.async.wait_group %0;\n" :: "n"(N));
}

// ---------------------------------------------------------------------------
// Prep kernels: fp32 -> fp16
// ---------------------------------------------------------------------------
__global__ void f2h_kernel(const float4* __restrict__ in, __half2* __restrict__ out, int n4) {
    int i = blockIdx.x * blockDim.x + threadIdx.x;
    if (i < n4) {
        float4 v = in[i];
        out[i * 2 + 0] = __floats2half2_rn(v.x, v.y);
        out[i * 2 + 1] = __floats2half2_rn(v.z, v.w);
    }
}

__global__ void transpose_h(const float* __restrict__ in, __half* __restrict__ out,
                            int R, int C) {
    __shared__ float t[32][33];
    const int bx = blockIdx.x * 32;
    const int by = blockIdx.y * 32;
#pragma unroll
    for (int i = 0; i < 4; i++) {
        int y = by + threadIdx.y + i * 8;
        t[threadIdx.y + i * 8][threadIdx.x] = in[(size_t)y * C + bx + threadIdx.x];
    }
    __syncthreads();
#pragma unroll
    for (int i = 0; i < 4; i++) {
        int oy = bx + threadIdx.y + i * 8;
        out[(size_t)oy * R + by + threadIdx.x] = __float2half_rn(t[threadIdx.x][threadIdx.y + i * 8]);
    }
}

// ---------------------------------------------------------------------------
// FP16 TN GEMM + bias (unchanged — known good)
// ---------------------------------------------------------------------------
#define GK     32
#define STG    4
#define TILE_B (128 * GK * 2)
#define GEMM_SMEM_BYTES (2 * STG * TILE_B)

template <bool HALF_OUT>
__global__ __launch_bounds__(256, 2) void gemm_h(
    const __half* __restrict__ A,
    const __half* __restrict__ BT,
    const float* __restrict__ bias,
    void* __restrict__ Cout,
    int M, int N, int K)
{
    extern __shared__ char smem[];
    const uint32_t As_s = sptr(smem);
    const uint32_t Bs_s = As_s + STG * TILE_B;

    const int tid  = threadIdx.x;
    const int wid  = tid >> 5;
    const int lane = tid & 31;
    const int grp  = lane >> 2;
    const int tig  = lane & 3;

    const int m0 = blockIdx.y * 128;
    const int n0 = blockIdx.x * 128;
    const int wm = (wid & 1) * 64;
    const int wn = (wid >> 1) * 32;

    const int a_row = lane & 15;
    const int a_ch  = (lane >> 4);
    const int b_row = (lane & 7) + ((lane >> 4) & 1) * 8;
    const int b_ch  = (lane >> 3) & 1;

    float acc[4][4][4];
#pragma unroll
    for (int i = 0; i < 4; i++)
#pragma unroll
        for (int j = 0; j < 4; j++)
#pragma unroll
            for (int r = 0; r < 4; r++) acc[i][j][r] = 0.0f;

    const int nk = K / GK;

    auto issue = [&](int t) {
        const int s = t % STG;
        const uint32_t ab = As_s + (uint32_t)s * TILE_B;
        const uint32_t bb = Bs_s + (uint32_t)s * TILE_B;
        const int k0 = t * GK;
#pragma unroll
        for (int i = 0; i < 2; i++) {
            const int g = tid + i * 256;
            const int r = g >> 2;
            const int c = g & 3;
            const uint32_t so = (uint32_t)(r * 64 + ((c ^ ((r >> 1) & 3)) << 4));
            cp16(ab + so, &A [(size_t)(m0 + r) * K + k0 + c * 8]);
            cp16(bb + so, &BT[(size_t)(n0 + r) * K + k0 + c * 8]);
        }
    };

#pragma unroll
    for (int t = 0; t < STG - 1; t++) {
        issue(t);
        cp_commit();
    }

    for (int t = 0; t < nk; t++) {
        const int pre = t + STG - 1;
        if (pre < nk) issue(pre);
        cp_commit();
        cp_wait<STG - 1>();
        __syncthreads();

        const int s = t % STG;
        const uint32_t ab = As_s + (uint32_t)s * TILE_B;
        const uint32_t bb = Bs_s + (uint32_t)s * TILE_B;

#pragma unroll
        for (int ks = 0; ks < 2; ks++) {
            const int kc = ks * 2;
            uint32_t a[4][4];
            uint32_t b[4][2];
#pragma unroll
            for (int mf = 0; mf < 4; mf++) {
                const int r = wm + mf * 16 + a_row;
                ldsm4(a[mf][0], a[mf][1], a[mf][2], a[mf][3],
                      ab + (uint32_t)(r * 64 + (((kc + a_ch) ^ ((r >> 1) & 3)) << 4)));
            }
#pragma unroll
            for (int p = 0; p < 2; p++) {
                const int r = wn + p * 16 + b_row;
                ldsm4(b[2 * p][0], b[2 * p][1], b[2 * p + 1][0], b[2 * p + 1][1],
                      bb + (uint32_t)(r * 64 + (((kc + b_ch) ^ ((r >> 1) & 3)) << 4)));
            }
#pragma unroll
            for (int mf = 0; mf < 4; mf++)
#pragma unroll
                for (int nf = 0; nf < 4; nf++)
                    mma_f16(acc[mf][nf],
                            a[mf][0], a[mf][1], a[mf][2], a[mf][3],
                            b[nf][0], b[nf][1]);
        }
        __syncthreads();
    }

#pragma unroll
    for (int nf = 0; nf < 4; nf++) {
        const int col = n0 + wn + nf * 8 + tig * 2;
        const float bx = bias[col];
        const float by = bias[col + 1];
#pragma unroll
        for (int mf = 0; mf < 4; mf++) {
            const int row0 = m0 + wm + mf * 16 + grp;
            const int row1 = row0 + 8;
            const float o00 = acc[mf][nf][0] + bx;
            const float o01 = acc[mf][nf][1] + by;
            const float o10 = acc[mf][nf][2] + bx;
            const float o11 = acc[mf][nf][3] + by;
            if (HALF_OUT) {
                __half2* Ch = (__half2*)Cout;
                Ch[((size_t)row0 * N + col) >> 1] = __floats2half2_rn(o00, o01);
                Ch[((size_t)row1 * N + col) >> 1] = __floats2half2_rn(o10, o11);
            } else {
                float* Cf = (float*)Cout;
                *(float2*)&Cf[(size_t)row0 * N + col] = make_float2(o00, o01);
                *(float2*)&Cf[(size_t)row1 * N + col] = make_float2(o10, o11);
            }
        }
    }
}

// ---------------------------------------------------------------------------
// FP16 flash attention: register-resident P (S C-fragment == P A-fragment),
// double-buffered K/V, exp2 softmax, heavy-first q-tile order.
// ---------------------------------------------------------------------------
#define PADH 72
#define KV_STAGE_H (2 * 64 * PADH)
#define ATTN_SMEM_BYTES ((2 * KV_STAGE_H + 8 * 16 * PADH) * 2)

__global__ __launch_bounds__(256, 2) void attn_h(
    const __half* __restrict__ qkv, __half* __restrict__ y)
{
    extern __shared__ char smc[];
    __half* KV = (__half*)smc;                     // [2][ K(64xPADH) | V(64xPADH) ]
    __half* Ps = KV + 2 * KV_STAGE_H;              // [8][16][PADH] Q staging only

    const int tid  = threadIdx.x;
    const int wid  = tid >> 5;
    const int lane = tid & 31;
    const int grp  = lane >> 2;
    const int tig  = lane & 3;

    const int qt = (gridDim.x - 1) - blockIdx.x;   // heavy tiles first
    const int h  = blockIdx.y;
    const int b  = blockIdx.z;
    const int q0 = qt * 128;
    const int wm = wid * 16;

    const __half* base = qkv + (size_t)b * Td * C3 + h * 192;
    __half* Pw = Ps + wid * 16 * PADH;
    const uint32_t Pw_s = sptr(Pw);
    const uint32_t KV_s = sptr(KV);

    const int a_row = lane & 15;
    const int a_c8  = (lane >> 4) * 8;
    const int b_row = (lane & 7) + ((lane >> 4) & 1) * 8;
    const int b_c8  = ((lane >> 3) & 1) * 8;
    const int v_row = lane & 15;
    const int v_c8  = (lane >> 4) * 8;

    // stage Q scaled by 0.125*log2(e) (exp2 domain)
    const __half2 hs = __float2half2_rn(0.125f * 1.44269504f);
#pragma unroll
    for (int i = 0; i < 4; i++) {
        const int f = i * 32 + lane;
        const int r = f >> 3, c8 = (f & 7) * 8;
        uint4 v = *(const uint4*)(base + (size_t)(q0 + wm + r) * C3 + c8);
        __half2* hv = (__half2*)&v;
#pragma unroll
        for (int u = 0; u < 4; u++) hv[u] = __hmul2(hv[u], hs);
        *(uint4*)&Pw[r * PADH + c8] = v;
    }
    __syncwarp();

    uint32_t Qa[4][4];
#pragma unroll
    for (int k = 0; k < 4; k++)
        ldsm4(Qa[k][0], Qa[k][1], Qa[k][2], Qa[k][3],
              Pw_s + (uint32_t)(a_row * PADH + k * 16 + a_c8) * 2u);

    float o[8][4];
#pragma unroll
    for (int nf = 0; nf < 8; nf++)
#pragma unroll
        for (int r = 0; r < 4; r++) o[nf][r] = 0.0f;

    float mx0 = -CUDART_INF_F, mx1 = -CUDART_INF_F;
    float l0 = 0.0f, l1 = 0.0f;

    const int row0 = q0 + wm + grp;
    const int row1 = row0 + 8;
    const int nkt  = 2 * (qt + 1);

    auto issue_kv = [&](int kt) {
        const uint32_t sb = KV_s + (uint32_t)((kt & 1) * KV_STAGE_H) * 2u;
        const int k0 = kt * 64;
#pragma unroll
        for (int i = 0; i < 2; i++) {
            const int g = tid + i * 256;
            const int j = g >> 3, c8 = (g & 7) * 8;
            const uint32_t dst = (uint32_t)(j * PADH + c8) * 2u;
            cp16(sb + dst,                              base + (size_t)(k0 + j) * C3 + 64 + c8);
            cp16(sb + (uint32_t)(64 * PADH) * 2u + dst, base + (size_t)(k0 + j) * C3 + 128 + c8);
        }
    };

    issue_kv(0);
    cp_commit();

    for (int kt = 0; kt < nkt; kt++) {
        if (kt + 1 < nkt) {
            issue_kv(kt + 1);
            cp_commit();
            cp_wait<1>();
        } else {
            cp_wait<0>();
        }
        __syncthreads();

        const uint32_t Ks_s = KV_s + (uint32_t)((kt & 1) * KV_STAGE_H) * 2u;
        const uint32_t Vs_s = Ks_s + (uint32_t)(64 * PADH) * 2u;
        const int k0 = kt * 64;

        // S = Q @ K^T  (exp2 domain)
        float sc[8][4];
#pragma unroll
        for (int nf = 0; nf < 8; nf++)
#pragma unroll
            for (int r = 0; r < 4; r++) sc[nf][r] = 0.0f;

#pragma unroll
        for (int k = 0; k < 4; k++) {
            uint32_t bf[8][2];
#pragma unroll
            for (int p = 0; p < 4; p++)
                ldsm4(bf[2 * p][0], bf[2 * p][1], bf[2 * p + 1][0], bf[2 * p + 1][1],
                      Ks_s + (uint32_t)((p * 16 + b_row) * PADH + k * 16 + b_c8) * 2u);
#pragma unroll
            for (int nf = 0; nf < 8; nf++)
                mma_f16(sc[nf], Qa[k][0], Qa[k][1], Qa[k][2], Qa[k][3],
                        bf[nf][0], bf[nf][1]);
        }

        // causal mask
        if (k0 + 64 > q0) {
#pragma unroll
            for (int nf = 0; nf < 8; nf++) {
                const int c = k0 + nf * 8 + tig * 2;
                if (c     > row0) sc[nf][0] = -CUDART_INF_F;
                if (c + 1 > row0) sc[nf][1] = -CUDART_INF_F;
                if (c     > row1) sc[nf][2] = -CUDART_INF_F;
                if (c + 1 > row1) sc[nf][3] = -CUDART_INF_F;
            }
        }

        // online softmax (base-2)
        float mt0 = -CUDART_INF_F, mt1 = -CUDART_INF_F;
#pragma unroll
        for (int nf = 0; nf < 8; nf++) {
            mt0 = fmaxf(mt0, fmaxf(sc[nf][0], sc[nf][1]));
            mt1 = fmaxf(mt1, fmaxf(sc[nf][2], sc[nf][3]));
        }
        mt0 = fmaxf(mt0, __shfl_xor_sync(0xffffffffu, mt0, 1));
        mt0 = fmaxf(mt0, __shfl_xor_sync(0xffffffffu, mt0, 2));
        mt1 = fmaxf(mt1, __shfl_xor_sync(0xffffffffu, mt1, 1));
        mt1 = fmaxf(mt1, __shfl_xor_sync(0xffffffffu, mt1, 2));

        const float mn0 = fmaxf(mx0, mt0);
        const float mn1 = fmaxf(mx1, mt1);
        const float corr0 = fexp2(mx0 - mn0);
        const float corr1 = fexp2(mx1 - mn1);

        // P in registers: A-fragment of P == C-fragment layout of S.
        // pa[k] covers j-cols [k*16, k*16+16) = S blocks 2k, 2k+1.
        uint32_t pa[4][4];
        float ls0 = 0.0f, ls1 = 0.0f;
#pragma unroll
        for (int nf = 0; nf < 8; nf++) {
            const float p0 = fexp2(sc[nf][0] - mn0);
            const float p1 = fexp2(sc[nf][1] - mn0);
            const float p2 = fexp2(sc[nf][2] - mn1);
            const float p3 = fexp2(sc[nf][3] - mn1);
            ls0 += p0 + p1;
            ls1 += p2 + p3;
            const int k = nf >> 1, s = (nf & 1) * 2;
            pa[k][s + 0] = packh2(p0, p1);
            pa[k][s + 1] = packh2(p2, p3);
        }
        ls0 += __shfl_xor_sync(0xffffffffu, ls0, 1);
        ls0 += __shfl_xor_sync(0xffffffffu, ls0, 2);
        ls1 += __shfl_xor_sync(0xffffffffu, ls1, 1);
        ls1 += __shfl_xor_sync(0xffffffffu, ls1, 2);

        l0 = l0 * corr0 + ls0;
        l1 = l1 * corr1 + ls1;
        mx0 = mn0; mx1 = mn1;

#pragma unroll
        for (int nf = 0; nf < 8; nf++) {
            o[nf][0] *= corr0; o[nf][1] *= corr0;
            o[nf][2] *= corr1; o[nf][3] *= corr1;
        }

        // O += P @ V  (P straight from registers; V via ldmatrix.trans)
#pragma unroll
        for (int k = 0; k < 4; k++) {
            uint32_t bf[8][2];
#pragma unroll
            for (int p = 0; p < 4; p++)
                ldsm4t(bf[2 * p][0], bf[2 * p][1], bf[2 * p + 1][0], bf[2 * p + 1][1],
                       Vs_s + (uint32_t)((k * 16 + v_row) * PADH + p * 16 + v_c8) * 2u);
#pragma unroll
            for (int nf = 0; nf < 8; nf++)
                mma_f16(o[nf], pa[k][0], pa[k][1], pa[k][2], pa[k][3],
                        bf[nf][0], bf[nf][1]);
        }
        __syncthreads();   // stage kt&1 fully consumed before re-issue
    }

    const float inv0 = 1.0f / l0;
    const float inv1 = 1.0f / l1;
    __half* yr = y + ((size_t)b * Td + q0 + wm) * Cd + h * HDd;
#pragma unroll
    for (int nf = 0; nf < 8; nf++) {
        const int c = nf * 8 + tig * 2;
        *(__half2*)&yr[(size_t)grp * Cd + c] =
            __floats2half2_rn(o[nf][0] * inv0, o[nf][1] * inv0);
        *(__half2*)&yr[(size_t)(grp + 8) * Cd + c] =
            __floats2half2_rn(o[nf][2] * inv1, o[nf][3] * inv1);
    }
}

// ---------------------------------------------------------------------------
extern "C" void kernel_launch(void* const* d_in, const int* in_sizes, int n_in,
                              void* d_out, int out_size)
{
    const float* x  = (const float*)d_in[0];
    const float* Wa = (const float*)d_in[1];
    const float* ba = (const float*)d_in[2];
    const float* Wp = (const float*)d_in[3];
    const float* bp = (const float*)d_in[4];
    float* out = (float*)d_out;

    __half *qkvh, *yh, *xh, *wah, *wph;
    cudaGetSymbolAddress((void**)&qkvh, g_qkvh);
    cudaGetSymbolAddress((void**)&yh,   g_yh);
    cudaGetSymbolAddress((void**)&xh,   g_xh);
    cudaGetSymbolAddress((void**)&wah,  g_wah);
    cudaGetSymbolAddress((void**)&wph,  g_wph);

    cudaFuncSetAttribute(gemm_h<true>,  cudaFuncAttributeMaxDynamicSharedMemorySize, GEMM_SMEM_BYTES);
    cudaFuncSetAttribute(gemm_h<false>, cudaFuncAttributeMaxDynamicSharedMemorySize, GEMM_SMEM_BYTES);
    cudaFuncSetAttribute(attn_h,        cudaFuncAttributeMaxDynamicSharedMemorySize, ATTN_SMEM_BYTES);

    f2h_kernel<<<(Md * Cd / 4 + 255) / 256, 256>>>((const float4*)x, (__half2*)xh, Md * Cd / 4);
    transpose_h<<<dim3(C3 / 32, Cd / 32), dim3(32, 8)>>>(Wa, wah, Cd, C3);
    transpose_h<<<dim3(Cd / 32, Cd / 32), dim3(32, 8)>>>(Wp, wph, Cd, Cd);

    gemm_h<true><<<dim3(C3 / 128, Md / 128), 256, GEMM_SMEM_BYTES>>>(
        xh, wah, ba, qkvh, Md, C3, Cd);

    attn_h<<<dim3(Td / 128, Hd, Bd), 256, ATTN_SMEM_BYTES>>>(qkvh, yh);

    gemm_h<false><<<dim3(Cd / 128, Md / 128), 256, GEMM_SMEM_BYTES>>>(
        yh, wph, bp, out, Md, Cd, Cd);
}

// round 11
// speedup vs baseline: 8.5518x; 1.0336x over previous
#include <cuda_runtime.h>
#include <cuda_fp16.h>
#include <math_constants.h>
#include <cstdint>

// Problem constants
#define Bd   8
#define Td   1024
#define Cd   768
#define Hd   12
#define HDd  64
#define C3   2304
#define Md   (Bd * Td)   // 8192

// Scratch (__device__ globals; allocation-free rule)
__device__ __half g_qkvh[(size_t)Md * C3];
__device__ __half g_yh  [(size_t)Md * Cd];
__device__ __half g_xh  [(size_t)Md * Cd];
__device__ __half g_wah [(size_t)C3 * Cd];   // W_attn^T [2304][768]
__device__ __half g_wph [(size_t)Cd * Cd];   // W_proj^T [768][768]

// ---------------------------------------------------------------------------
__device__ __forceinline__ uint32_t sptr(const void* p) {
    return (uint32_t)__cvta_generic_to_shared(p);
}

__device__ __forceinline__ float fexp2(float x) {
    float r;
    asm("ex2.approx.f32 %0, %1;" : "=f"(r) : "f"(x));
    return r;
}

// pack two floats into one f16x2 register (RN), lo=a, hi=b
__device__ __forceinline__ uint32_t packh2(float a, float b) {
    uint32_t r;
    asm("cvt.rn.f16x2.f32 %0, %1, %2;" : "=r"(r) : "f"(b), "f"(a));
    return r;
}

__device__ __forceinline__ void mma_f16(float c[4],
                                        uint32_t a0, uint32_t a1, uint32_t a2, uint32_t a3,
                                        uint32_t b0, uint32_t b1) {
    asm volatile(
        "mma.sync.aligned.m16n8k16.row.col.f32.f16.f16.f32 "
        "{%0,%1,%2,%3}, {%4,%5,%6,%7}, {%8,%9}, {%0,%1,%2,%3};"
        : "+f"(c[0]), "+f"(c[1]), "+f"(c[2]), "+f"(c[3])
        : "r"(a0), "r"(a1), "r"(a2), "r"(a3), "r"(b0), "r"(b1));
}

__device__ __forceinline__ void ldsm4(uint32_t& r0, uint32_t& r1,
                                      uint32_t& r2, uint32_t& r3, uint32_t addr) {
    asm volatile("ldmatrix.sync.aligned.m8n8.x4.shared.b16 {%0,%1,%2,%3}, [%4];"
                 : "=r"(r0), "=r"(r1), "=r"(r2), "=r"(r3) : "r"(addr));
}

__device__ __forceinline__ void ldsm4t(uint32_t& r0, uint32_t& r1,
                                       uint32_t& r2, uint32_t& r3, uint32_t addr) {
    asm volatile("ldmatrix.sync.aligned.m8n8.x4.trans.shared.b16 {%0,%1,%2,%3}, [%4];"
                 : "=r"(r0), "=r"(r1), "=r"(r2), "=r"(r3) : "r"(addr));
}

__device__ __forceinline__ void cp16(uint32_t dst, const void* src) {
    asm volatile("cp.async.cg.shared.global [%0], [%1], 16;\n" :: "r"(dst), "l"(src));
}
__device__ __forceinline__ void cp_commit() {
    asm volatile("cp.async.commit_group;\n");
}
template <int N>
__device__ __forceinline__ void cp_wait() {
    asm volatile("cp.async.wait_group %0;\n" :: "n"(N));
}

// ---------------------------------------------------------------------------
// Prep kernels: fp32 -> fp16
// ---------------------------------------------------------------------------
__global__ void f2h_kernel(const float4* __restrict__ in, __half2* __restrict__ out, int n4) {
    int i = blockIdx.x * blockDim.x + threadIdx.x;
    if (i < n4) {
        float4 v = in[i];
        out[i * 2 + 0] = __floats2half2_rn(v.x, v.y);
        out[i * 2 + 1] = __floats2half2_rn(v.z, v.w);
    }
}

__global__ void transpose_h(const float* __restrict__ in, __half* __restrict__ out,
                            int R, int C) {
    __shared__ float t[32][33];
    const int bx = blockIdx.x * 32;
    const int by = blockIdx.y * 32;
#pragma unroll
    for (int i = 0; i < 4; i++) {
        int y = by + threadIdx.y + i * 8;
        t[threadIdx.y + i * 8][threadIdx.x] = in[(size_t)y * C + bx + threadIdx.x];
    }
    __syncthreads();
#pragma unroll
    for (int i = 0; i < 4; i++) {
        int oy = bx + threadIdx.y + i * 8;
        out[(size_t)oy * R + by + threadIdx.x] = __float2half_rn(t[threadIdx.x][threadIdx.y + i * 8]);
    }
}

// ---------------------------------------------------------------------------
// FP16 TN GEMM + bias: single-sync multistage mainloop.
// ---------------------------------------------------------------------------
#define GK     32
#define STG    4
#define TILE_B (128 * GK * 2)
#define GEMM_SMEM_BYTES (2 * STG * TILE_B)

template <bool HALF_OUT>
__global__ __launch_bounds__(256, 2) void gemm_h(
    const __half* __restrict__ A,
    const __half* __restrict__ BT,
    const float* __restrict__ bias,
    void* __restrict__ Cout,
    int M, int N, int K)
{
    extern __shared__ char smem[];
    const uint32_t As_s = sptr(smem);
    const uint32_t Bs_s = As_s + STG * TILE_B;

    const int tid  = threadIdx.x;
    const int wid  = tid >> 5;
    const int lane = tid & 31;
    const int grp  = lane >> 2;
    const int tig  = lane & 3;

    const int m0 = blockIdx.y * 128;
    const int n0 = blockIdx.x * 128;
    const int wm = (wid & 1) * 64;
    const int wn = (wid >> 1) * 32;

    const int a_row = lane & 15;
    const int a_ch  = (lane >> 4);
    const int b_row = (lane & 7) + ((lane >> 4) & 1) * 8;
    const int b_ch  = (lane >> 3) & 1;

    float acc[4][4][4];
#pragma unroll
    for (int i = 0; i < 4; i++)
#pragma unroll
        for (int j = 0; j < 4; j++)
#pragma unroll
            for (int r = 0; r < 4; r++) acc[i][j][r] = 0.0f;

    const int nk = K / GK;

    auto issue = [&](int t) {
        const int s = t % STG;
        const uint32_t ab = As_s + (uint32_t)s * TILE_B;
        const uint32_t bb = Bs_s + (uint32_t)s * TILE_B;
        const int k0 = t * GK;
#pragma unroll
        for (int i = 0; i < 2; i++) {
            const int g = tid + i * 256;
            const int r = g >> 2;
            const int c = g & 3;
            const uint32_t so = (uint32_t)(r * 64 + ((c ^ ((r >> 1) & 3)) << 4));
            cp16(ab + so, &A [(size_t)(m0 + r) * K + k0 + c * 8]);
            cp16(bb + so, &BT[(size_t)(n0 + r) * K + k0 + c * 8]);
        }
    };

#pragma unroll
    for (int t = 0; t < STG - 1; t++) {
        issue(t);
        cp_commit();
    }

    for (int t = 0; t < nk; t++) {
        cp_wait<STG - 2>();        // stage t's group complete
        __syncthreads();           // visible to all warps; stage (t-1)%STG free
        const int pre = t + STG - 1;
        if (pre < nk) issue(pre);  // writes stage (t-1)%STG — safe after sync
        cp_commit();

        const int s = t % STG;
        const uint32_t ab = As_s + (uint32_t)s * TILE_B;
        const uint32_t bb = Bs_s + (uint32_t)s * TILE_B;

#pragma unroll
        for (int ks = 0; ks < 2; ks++) {
            const int kc = ks * 2;
            uint32_t a[4][4];
            uint32_t b[4][2];
#pragma unroll
            for (int mf = 0; mf < 4; mf++) {
                const int r = wm + mf * 16 + a_row;
                ldsm4(a[mf][0], a[mf][1], a[mf][2], a[mf][3],
                      ab + (uint32_t)(r * 64 + (((kc + a_ch) ^ ((r >> 1) & 3)) << 4)));
            }
#pragma unroll
            for (int p = 0; p < 2; p++) {
                const int r = wn + p * 16 + b_row;
                ldsm4(b[2 * p][0], b[2 * p][1], b[2 * p + 1][0], b[2 * p + 1][1],
                      bb + (uint32_t)(r * 64 + (((kc + b_ch) ^ ((r >> 1) & 3)) << 4)));
            }
#pragma unroll
            for (int mf = 0; mf < 4; mf++)
#pragma unroll
                for (int nf = 0; nf < 4; nf++)
                    mma_f16(acc[mf][nf],
                            a[mf][0], a[mf][1], a[mf][2], a[mf][3],
                            b[nf][0], b[nf][1]);
        }
    }

#pragma unroll
    for (int nf = 0; nf < 4; nf++) {
        const int col = n0 + wn + nf * 8 + tig * 2;
        const float bx = bias[col];
        const float by = bias[col + 1];
#pragma unroll
        for (int mf = 0; mf < 4; mf++) {
            const int row0 = m0 + wm + mf * 16 + grp;
            const int row1 = row0 + 8;
            const float o00 = acc[mf][nf][0] + bx;
            const float o01 = acc[mf][nf][1] + by;
            const float o10 = acc[mf][nf][2] + bx;
            const float o11 = acc[mf][nf][3] + by;
            if (HALF_OUT) {
                __half2* Ch = (__half2*)Cout;
                Ch[((size_t)row0 * N + col) >> 1] = __floats2half2_rn(o00, o01);
                Ch[((size_t)row1 * N + col) >> 1] = __floats2half2_rn(o10, o11);
            } else {
                float* Cf = (float*)Cout;
                *(float2*)&Cf[(size_t)row0 * N + col] = make_float2(o00, o01);
                *(float2*)&Cf[(size_t)row1 * N + col] = make_float2(o10, o11);
            }
        }
    }
}

// ---------------------------------------------------------------------------
// FP16 flash attention: 3-stage K/V ring, single sync per k-tile,
// register-resident P, exp2 softmax, heavy-first q-tile order.
// ---------------------------------------------------------------------------
#define PADH 72
#define ASTG 3
#define KV_STAGE_H (2 * 64 * PADH)
#define ATTN_SMEM_BYTES ((ASTG * KV_STAGE_H + 8 * 16 * PADH) * 2)

__global__ __launch_bounds__(256, 2) void attn_h(
    const __half* __restrict__ qkv, __half* __restrict__ y)
{
    extern __shared__ char smc[];
    __half* KV = (__half*)smc;                     // [3][ K(64xPADH) | V(64xPADH) ]
    __half* Ps = KV + ASTG * KV_STAGE_H;           // [8][16][PADH] Q staging only

    const int tid  = threadIdx.x;
    const int wid  = tid >> 5;
    const int lane = tid & 31;
    const int grp  = lane >> 2;
    const int tig  = lane & 3;

    const int qt = (gridDim.x - 1) - blockIdx.x;   // heavy tiles first
    const int h  = blockIdx.y;
    const int b  = blockIdx.z;
    const int q0 = qt * 128;
    const int wm = wid * 16;

    const __half* base = qkv + (size_t)b * Td * C3 + h * 192;
    __half* Pw = Ps + wid * 16 * PADH;
    const uint32_t Pw_s = sptr(Pw);
    const uint32_t KV_s = sptr(KV);

    const int a_row = lane & 15;
    const int a_c8  = (lane >> 4) * 8;
    const int b_row = (lane & 7) + ((lane >> 4) & 1) * 8;
    const int b_c8  = ((lane >> 3) & 1) * 8;
    const int v_row = lane & 15;
    const int v_c8  = (lane >> 4) * 8;

    // stage Q scaled by 0.125*log2(e) (exp2 domain)
    const __half2 hs = __float2half2_rn(0.125f * 1.44269504f);
#pragma unroll
    for (int i = 0; i < 4; i++) {
        const int f = i * 32 + lane;
        const int r = f >> 3, c8 = (f & 7) * 8;
        uint4 v = *(const uint4*)(base + (size_t)(q0 + wm + r) * C3 + c8);
        __half2* hv = (__half2*)&v;
#pragma unroll
        for (int u = 0; u < 4; u++) hv[u] = __hmul2(hv[u], hs);
        *(uint4*)&Pw[r * PADH + c8] = v;
    }
    __syncwarp();

    uint32_t Qa[4][4];
#pragma unroll
    for (int k = 0; k < 4; k++)
        ldsm4(Qa[k][0], Qa[k][1], Qa[k][2], Qa[k][3],
              Pw_s + (uint32_t)(a_row * PADH + k * 16 + a_c8) * 2u);

    float o[8][4];
#pragma unroll
    for (int nf = 0; nf < 8; nf++)
#pragma unroll
        for (int r = 0; r < 4; r++) o[nf][r] = 0.0f;

    float mx0 = -CUDART_INF_F, mx1 = -CUDART_INF_F;
    float l0 = 0.0f, l1 = 0.0f;

    const int row0 = q0 + wm + grp;
    const int row1 = row0 + 8;
    const int nkt  = 2 * (qt + 1);   // >= 2 always

    auto issue_kv = [&](int kt) {
        const uint32_t sb = KV_s + (uint32_t)((kt % ASTG) * KV_STAGE_H) * 2u;
        const int k0 = kt * 64;
#pragma unroll
        for (int i = 0; i < 2; i++) {
            const int g = tid + i * 256;
            const int j = g >> 3, c8 = (g & 7) * 8;
            const uint32_t dst = (uint32_t)(j * PADH + c8) * 2u;
            cp16(sb + dst,                              base + (size_t)(k0 + j) * C3 + 64 + c8);
            cp16(sb + (uint32_t)(64 * PADH) * 2u + dst, base + (size_t)(k0 + j) * C3 + 128 + c8);
        }
    };

    issue_kv(0);
    cp_commit();
    issue_kv(1);                      // nkt >= 2 always
    cp_commit();

    for (int kt = 0; kt < nkt; kt++) {
        cp_wait<1>();                 // group kt complete; kt+1 in flight
        __syncthreads();              // stage (kt+2)%3's readers (iter kt-1) done
        if (kt + 2 < nkt) issue_kv(kt + 2);
        cp_commit();

        const uint32_t Ks_s = KV_s + (uint32_t)((kt % ASTG) * KV_STAGE_H) * 2u;
        const uint32_t Vs_s = Ks_s + (uint32_t)(64 * PADH) * 2u;
        const int k0 = kt * 64;

        // S = Q @ K^T  (exp2 domain)
        float sc[8][4];
#pragma unroll
        for (int nf = 0; nf < 8; nf++)
#pragma unroll
            for (int r = 0; r < 4; r++) sc[nf][r] = 0.0f;

#pragma unroll
        for (int k = 0; k < 4; k++) {
            uint32_t bf[8][2];
#pragma unroll
            for (int p = 0; p < 4; p++)
                ldsm4(bf[2 * p][0], bf[2 * p][1], bf[2 * p + 1][0], bf[2 * p + 1][1],
                      Ks_s + (uint32_t)((p * 16 + b_row) * PADH + k * 16 + b_c8) * 2u);
#pragma unroll
            for (int nf = 0; nf < 8; nf++)
                mma_f16(sc[nf], Qa[k][0], Qa[k][1], Qa[k][2], Qa[k][3],
                        bf[nf][0], bf[nf][1]);
        }

        // causal mask
        if (k0 + 64 > q0) {
#pragma unroll
            for (int nf = 0; nf < 8; nf++) {
                const int c = k0 + nf * 8 + tig * 2;
                if (c     > row0) sc[nf][0] = -CUDART_INF_F;
                if (c + 1 > row0) sc[nf][1] = -CUDART_INF_F;
                if (c     > row1) sc[nf][2] = -CUDART_INF_F;
                if (c + 1 > row1) sc[nf][3] = -CUDART_INF_F;
            }
        }

        // online softmax (base-2)
        float mt0 = -CUDART_INF_F, mt1 = -CUDART_INF_F;
#pragma unroll
        for (int nf = 0; nf < 8; nf++) {
            mt0 = fmaxf(mt0, fmaxf(sc[nf][0], sc[nf][1]));
            mt1 = fmaxf(mt1, fmaxf(sc[nf][2], sc[nf][3]));
        }
        mt0 = fmaxf(mt0, __shfl_xor_sync(0xffffffffu, mt0, 1));
        mt0 = fmaxf(mt0, __shfl_xor_sync(0xffffffffu, mt0, 2));
        mt1 = fmaxf(mt1, __shfl_xor_sync(0xffffffffu, mt1, 1));
        mt1 = fmaxf(mt1, __shfl_xor_sync(0xffffffffu, mt1, 2));

        const float mn0 = fmaxf(mx0, mt0);
        const float mn1 = fmaxf(mx1, mt1);
        const float corr0 = fexp2(mx0 - mn0);
        const float corr1 = fexp2(mx1 - mn1);

        // P in registers: A-fragment of P == C-fragment layout of S.
        uint32_t pa[4][4];
        float ls0 = 0.0f, ls1 = 0.0f;
#pragma unroll
        for (int nf = 0; nf < 8; nf++) {
            const float p0 = fexp2(sc[nf][0] - mn0);
            const float p1 = fexp2(sc[nf][1] - mn0);
            const float p2 = fexp2(sc[nf][2] - mn1);
            const float p3 = fexp2(sc[nf][3] - mn1);
            ls0 += p0 + p1;
            ls1 += p2 + p3;
            const int k = nf >> 1, s = (nf & 1) * 2;
            pa[k][s + 0] = packh2(p0, p1);
            pa[k][s + 1] = packh2(p2, p3);
        }
        ls0 += __shfl_xor_sync(0xffffffffu, ls0, 1);
        ls0 += __shfl_xor_sync(0xffffffffu, ls0, 2);
        ls1 += __shfl_xor_sync(0xffffffffu, ls1, 1);
        ls1 += __shfl_xor_sync(0xffffffffu, ls1, 2);

        l0 = l0 * corr0 + ls0;
        l1 = l1 * corr1 + ls1;
        mx0 = mn0; mx1 = mn1;

#pragma unroll
        for (int nf = 0; nf < 8; nf++) {
            o[nf][0] *= corr0; o[nf][1] *= corr0;
            o[nf][2] *= corr1; o[nf][3] *= corr1;
        }

        // O += P @ V  (P from registers; V via ldmatrix.trans)
#pragma unroll
        for (int k = 0; k < 4; k++) {
            uint32_t bf[8][2];
#pragma unroll
            for (int p = 0; p < 4; p++)
                ldsm4t(bf[2 * p][0], bf[2 * p][1], bf[2 * p + 1][0], bf[2 * p + 1][1],
                       Vs_s + (uint32_t)((k * 16 + v_row) * PADH + p * 16 + v_c8) * 2u);
#pragma unroll
            for (int nf = 0; nf < 8; nf++)
                mma_f16(o[nf], pa[k][0], pa[k][1], pa[k][2], pa[k][3],
                        bf[nf][0], bf[nf][1]);
        }
        // no trailing sync: 3-stage ring + top-of-loop sync covers reuse
    }

    const float inv0 = 1.0f / l0;
    const float inv1 = 1.0f / l1;
    __half* yr = y + ((size_t)b * Td + q0 + wm) * Cd + h * HDd;
#pragma unroll
    for (int nf = 0; nf < 8; nf++) {
        const int c = nf * 8 + tig * 2;
        *(__half2*)&yr[(size_t)grp * Cd + c] =
            __floats2half2_rn(o[nf][0] * inv0, o[nf][1] * inv0);
        *(__half2*)&yr[(size_t)(grp + 8) * Cd + c] =
            __floats2half2_rn(o[nf][2] * inv1, o[nf][3] * inv1);
    }
}

// ---------------------------------------------------------------------------
extern "C" void kernel_launch(void* const* d_in, const int* in_sizes, int n_in,
                              void* d_out, int out_size)
{
    const float* x  = (const float*)d_in[0];
    const float* Wa = (const float*)d_in[1];
    const float* ba = (const float*)d_in[2];
    const float* Wp = (const float*)d_in[3];
    const float* bp = (const float*)d_in[4];
    float* out = (float*)d_out;

    __half *qkvh, *yh, *xh, *wah, *wph;
    cudaGetSymbolAddress((void**)&qkvh, g_qkvh);
    cudaGetSymbolAddress((void**)&yh,   g_yh);
    cudaGetSymbolAddress((void**)&xh,   g_xh);
    cudaGetSymbolAddress((void**)&wah,  g_wah);
    cudaGetSymbolAddress((void**)&wph,  g_wph);

    cudaFuncSetAttribute(gemm_h<true>,  cudaFuncAttributeMaxDynamicSharedMemorySize, GEMM_SMEM_BYTES);
    cudaFuncSetAttribute(gemm_h<false>, cudaFuncAttributeMaxDynamicSharedMemorySize, GEMM_SMEM_BYTES);
    cudaFuncSetAttribute(attn_h,        cudaFuncAttributeMaxDynamicSharedMemorySize, ATTN_SMEM_BYTES);

    f2h_kernel<<<(Md * Cd / 4 + 255) / 256, 256>>>((const float4*)x, (__half2*)xh, Md * Cd / 4);
    transpose_h<<<dim3(C3 / 32, Cd / 32), dim3(32, 8)>>>(Wa, wah, Cd, C3);
    transpose_h<<<dim3(Cd / 32, Cd / 32), dim3(32, 8)>>>(Wp, wph, Cd, Cd);

    gemm_h<true><<<dim3(C3 / 128, Md / 128), 256, GEMM_SMEM_BYTES>>>(
        xh, wah, ba, qkvh, Md, C3, Cd);

    attn_h<<<dim3(Td / 128, Hd, Bd), 256, ATTN_SMEM_BYTES>>>(qkvh, yh);

    gemm_h<false><<<dim3(Cd / 128, Md / 128), 256, GEMM_SMEM_BYTES>>>(
        yh, wph, bp, out, Md, Cd, Cd);
}